// round 1
// baseline (speedup 1.0000x reference)
#include <cuda_runtime.h>

// Problem constants: B=8, C=256, H=W=32 -> N=1024, heads=8, hd=32, groups=8.
#define BATCH   8
#define CCH     256
#define NSP     1024
#define HEADS   8
#define HD      32

// Scratch (device globals; no allocation APIs allowed)
__device__ float g_h[BATCH * CCH * NSP];        // group-normed input   [b][c][n]
__device__ float g_qkv[BATCH * 3 * CCH * NSP];  // qkv                  [b][o][n]
__device__ float g_att[BATCH * CCH * NSP];      // attention output     [b][c][n]

// ---------------------------------------------------------------------------
// Kernel 1: GroupNorm. One block per (b, group); 32 channels x 1024 = 32768.
// ---------------------------------------------------------------------------
__global__ void gn_kernel(const float* __restrict__ x,
                          const float* __restrict__ sc,
                          const float* __restrict__ bi) {
    int bg = blockIdx.x;            // b*8 + g
    int g  = bg & 7;
    const float* xp = x   + (size_t)bg * 32 * NSP;
    float*       hp = g_h + (size_t)bg * 32 * NSP;

    int t = threadIdx.x;
    float s = 0.f, s2 = 0.f;
    for (int i = t; i < 32 * NSP; i += 256) {
        float v = xp[i];
        s += v; s2 += v * v;
    }
    __shared__ float r1[256], r2[256];
    r1[t] = s; r2[t] = s2;
    __syncthreads();
    for (int st = 128; st > 0; st >>= 1) {
        if (t < st) { r1[t] += r1[t + st]; r2[t] += r2[t + st]; }
        __syncthreads();
    }
    float mean = r1[0] * (1.f / 32768.f);
    float var  = r2[0] * (1.f / 32768.f) - mean * mean;
    float inv  = rsqrtf(var + 1e-5f);

    for (int i = t; i < 32 * NSP; i += 256) {
        int c = g * 32 + (i >> 10);
        hp[i] = (xp[i] - mean) * inv * sc[c] + bi[c];
    }
}

// ---------------------------------------------------------------------------
// Kernel 2/4: batched SGEMM  out[b][m][n] = sum_c W[m][c]*src[b][c][n] + bias[m]
// (+ optional residual). Block tile 64x64, K tile 16, 4x4 per thread.
// grid: (N/64, M/64, B), block: 256.
// ---------------------------------------------------------------------------
__global__ void gemm_kernel(const float* __restrict__ W,
                            const float* __restrict__ bias,
                            const float* __restrict__ src,
                            const float* __restrict__ resid,
                            float* __restrict__ out, int M) {
    int b  = blockIdx.z;
    const float* Bp = src + (size_t)b * CCH * NSP;
    int m0 = blockIdx.y * 64, n0 = blockIdx.x * 64;

    __shared__ float As[16][64];   // [k][m]
    __shared__ float Bs[16][64];   // [k][n]

    int tid = threadIdx.x;
    int tx = tid & 15, ty = tid >> 4;

    // load indices
    int wm = tid >> 2;            // 0..63  (m)
    int wk = (tid & 3) * 4;       // 0,4,8,12
    int bk = tid >> 4;            // 0..15  (k)
    int bn = (tid & 15) * 4;      // n

    float acc[4][4] = {};

    for (int k0 = 0; k0 < CCH; k0 += 16) {
        float4 wv = *(const float4*)&W[(size_t)(m0 + wm) * CCH + k0 + wk];
        float4 bv = *(const float4*)&Bp[(size_t)(k0 + bk) * NSP + n0 + bn];
        As[wk + 0][wm] = wv.x;
        As[wk + 1][wm] = wv.y;
        As[wk + 2][wm] = wv.z;
        As[wk + 3][wm] = wv.w;
        *(float4*)&Bs[bk][bn] = bv;
        __syncthreads();

        #pragma unroll
        for (int kk = 0; kk < 16; kk++) {
            float4 a  = *(const float4*)&As[kk][ty * 4];
            float4 bb = *(const float4*)&Bs[kk][tx * 4];
            float av[4] = {a.x, a.y, a.z, a.w};
            float bw[4] = {bb.x, bb.y, bb.z, bb.w};
            #pragma unroll
            for (int i = 0; i < 4; i++)
                #pragma unroll
                for (int j = 0; j < 4; j++)
                    acc[i][j] += av[i] * bw[j];
        }
        __syncthreads();
    }

    #pragma unroll
    for (int i = 0; i < 4; i++) {
        int m = m0 + ty * 4 + i;
        float bsv = bias[m];
        size_t base = (size_t)b * M * NSP + (size_t)m * NSP + n0 + tx * 4;
        float4 o;
        o.x = acc[i][0] + bsv;
        o.y = acc[i][1] + bsv;
        o.z = acc[i][2] + bsv;
        o.w = acc[i][3] + bsv;
        if (resid) {
            float4 r = *(const float4*)&resid[base];
            o.x += r.x; o.y += r.y; o.z += r.z; o.w += r.w;
        }
        *(float4*)&out[base] = o;
    }
}

// ---------------------------------------------------------------------------
// Kernel 3: attention. One block per (b, head, 64-query tile).
// Flash-style online softmax over 16 K/V tiles of 64.
// grid: 1024 blocks, 256 threads.
// ---------------------------------------------------------------------------
__global__ void attn_kernel() {
    int blk = blockIdx.x;
    int qt  = blk & 15;          // query tile
    int bh  = blk >> 4;          // b*8 + h
    const float* qb = g_qkv + (size_t)(bh >> 3) * 3 * CCH * NSP
                            + (size_t)((bh & 7) * HD) * NSP;
    const float* kb = qb + (size_t)CCH * NSP;
    const float* vb = kb + (size_t)CCH * NSP;
    int n0 = qt * 64;

    __shared__ float Qs[32][65];
    __shared__ float Ks[32][65];
    __shared__ float Vs[32][65];
    __shared__ float Ss[64][65];

    int tid = threadIdx.x;
    // Load Q tile [32 dims][64 queries]
    for (int i = tid; i < 2048; i += 256) {
        int d = i >> 6, q = i & 63;
        Qs[d][q] = qb[d * NSP + n0 + q];
    }

    int tx = tid & 15, ty = tid >> 4;    // S compute: 16x16 threads, 4x4 each
    int qr = tid >> 2, seg = tid & 3;    // softmax/O:  4 threads per query row

    float m_i = -1e30f, l_i = 0.f;
    float acc[8] = {};
    const float scale = 0.17677669529663687f;  // 1/sqrt(32)

    for (int kt = 0; kt < 16; kt++) {
        __syncthreads();   // protect Ks/Vs/Ss from previous iteration readers
        int m0 = kt * 64;
        for (int i = tid; i < 2048; i += 256) {
            int d = i >> 6, m = i & 63;
            Ks[d][m] = kb[d * NSP + m0 + m];
            Vs[d][m] = vb[d * NSP + m0 + m];
        }
        __syncthreads();

        // S = Q^T K (scaled): each thread a 4x4 tile
        float s[4][4] = {};
        #pragma unroll
        for (int d = 0; d < 32; d++) {
            float a0 = Qs[d][ty * 4 + 0], a1 = Qs[d][ty * 4 + 1];
            float a2 = Qs[d][ty * 4 + 2], a3 = Qs[d][ty * 4 + 3];
            float b0 = Ks[d][tx * 4 + 0], b1 = Ks[d][tx * 4 + 1];
            float b2 = Ks[d][tx * 4 + 2], b3 = Ks[d][tx * 4 + 3];
            s[0][0] += a0 * b0; s[0][1] += a0 * b1; s[0][2] += a0 * b2; s[0][3] += a0 * b3;
            s[1][0] += a1 * b0; s[1][1] += a1 * b1; s[1][2] += a1 * b2; s[1][3] += a1 * b3;
            s[2][0] += a2 * b0; s[2][1] += a2 * b1; s[2][2] += a2 * b2; s[2][3] += a2 * b3;
            s[3][0] += a3 * b0; s[3][1] += a3 * b1; s[3][2] += a3 * b2; s[3][3] += a3 * b3;
        }
        #pragma unroll
        for (int i = 0; i < 4; i++)
            #pragma unroll
            for (int j = 0; j < 4; j++)
                Ss[ty * 4 + i][tx * 4 + j] = s[i][j] * scale;
        __syncthreads();

        // Online softmax: 4 threads (seg 0..3) own query row qr; 16 cols each.
        int mbase = seg * 16;
        float mx = -1e30f;
        #pragma unroll
        for (int m = 0; m < 16; m++) mx = fmaxf(mx, Ss[qr][mbase + m]);
        mx = fmaxf(mx, __shfl_xor_sync(0xffffffffu, mx, 1));
        mx = fmaxf(mx, __shfl_xor_sync(0xffffffffu, mx, 2));
        float m_new = fmaxf(m_i, mx);
        float corr  = __expf(m_i - m_new);
        float lsum = 0.f;
        #pragma unroll
        for (int m = 0; m < 16; m++) {
            float p = __expf(Ss[qr][mbase + m] - m_new);
            Ss[qr][mbase + m] = p;
            lsum += p;
        }
        lsum += __shfl_xor_sync(0xffffffffu, lsum, 1);
        lsum += __shfl_xor_sync(0xffffffffu, lsum, 2);
        l_i = l_i * corr + lsum;
        m_i = m_new;
        #pragma unroll
        for (int d = 0; d < 8; d++) acc[d] *= corr;
        __syncwarp();  // row's 4 lanes are in the same warp; P writes now visible

        // O += P @ V^T : thread (qr,seg) owns dims [seg*8, seg*8+8)
        int dbase = seg * 8;
        #pragma unroll 4
        for (int m = 0; m < 64; m++) {
            float p = Ss[qr][m];
            #pragma unroll
            for (int d = 0; d < 8; d++) acc[d] += p * Vs[dbase + d][m];
        }
    }

    float inv = 1.f / l_i;
    int dbase = seg * 8;
    float* op = g_att + (size_t)bh * HD * NSP;   // (b*256 + h*32)*1024
    #pragma unroll
    for (int d = 0; d < 8; d++)
        op[(size_t)(dbase + d) * NSP + n0 + qr] = acc[d] * inv;
}

// ---------------------------------------------------------------------------
extern "C" void kernel_launch(void* const* d_in, const int* in_sizes, int n_in,
                              void* d_out, int out_size) {
    const float* x        = (const float*)d_in[0];
    const float* gn_scale = (const float*)d_in[1];
    const float* gn_bias  = (const float*)d_in[2];
    const float* w_qkv    = (const float*)d_in[3];
    const float* b_qkv    = (const float*)d_in[4];
    const float* w_out    = (const float*)d_in[5];
    const float* b_out    = (const float*)d_in[6];
    float* out = (float*)d_out;

    float *ph, *pqkv, *patt;
    cudaGetSymbolAddress((void**)&ph,   g_h);
    cudaGetSymbolAddress((void**)&pqkv, g_qkv);
    cudaGetSymbolAddress((void**)&patt, g_att);

    // 1. GroupNorm
    gn_kernel<<<BATCH * 8, 256>>>(x, gn_scale, gn_bias);
    // 2. QKV projection: [768,256] @ [256,1024] per batch
    gemm_kernel<<<dim3(16, 12, BATCH), 256>>>(w_qkv, b_qkv, ph, nullptr, pqkv, 768);
    // 3. Attention
    attn_kernel<<<BATCH * HEADS * 16, 256>>>();
    // 4. Output projection + residual
    gemm_kernel<<<dim3(16, 4, BATCH), 256>>>(w_out, b_out, patt, x, out, 256);
}

// round 2
// speedup vs baseline: 1.4673x; 1.4673x over previous
#include <cuda_runtime.h>

// Problem constants: B=8, C=256, H=W=32 -> N=1024, heads=8, hd=32, groups=8.
#define BATCH   8
#define CCH     256
#define NSP     1024
#define HEADS   8
#define HD      32

typedef unsigned long long ULL;

// ---- packed f32x2 helpers (sm_103a FFMA2 path, PTX-only) -------------------
__device__ __forceinline__ ULL pk2(float lo, float hi) {
    ULL r; asm("mov.b64 %0, {%1,%2};" : "=l"(r) : "f"(lo), "f"(hi)); return r;
}
__device__ __forceinline__ float2 upk2(ULL v) {
    float2 f; asm("mov.b64 {%0,%1}, %2;" : "=f"(f.x), "=f"(f.y) : "l"(v)); return f;
}
__device__ __forceinline__ ULL dup2(float x) { return pk2(x, x); }
__device__ __forceinline__ ULL ffma2(ULL a, ULL b, ULL c) {
    ULL d; asm("fma.rn.f32x2 %0, %1, %2, %3;" : "=l"(d) : "l"(a), "l"(b), "l"(c));
    return d;
}
__device__ __forceinline__ ULL fmul2(ULL a, ULL b) {
    ULL d; asm("mul.rn.f32x2 %0, %1, %2;" : "=l"(d) : "l"(a), "l"(b)); return d;
}

// Scratch (device globals; no allocation APIs allowed)
__device__ float g_h[BATCH * CCH * NSP];        // group-normed input   [b][c][n]
__device__ float g_qkv[BATCH * 3 * CCH * NSP];  // qkv                  [b][o][n]
__device__ float g_att[BATCH * CCH * NSP];      // attention output     [b][c][n]

// ---------------------------------------------------------------------------
// Kernel 1: GroupNorm. One block per (b, group); 32 channels x 1024 = 32768.
// ---------------------------------------------------------------------------
__global__ void gn_kernel(const float* __restrict__ x,
                          const float* __restrict__ sc,
                          const float* __restrict__ bi) {
    int bg = blockIdx.x;            // b*8 + g
    int g  = bg & 7;
    const float4* xp = (const float4*)(x + (size_t)bg * 32 * NSP);
    float4*       hp = (float4*)(g_h + (size_t)bg * 32 * NSP);

    int t = threadIdx.x;
    float s = 0.f, s2 = 0.f;
    for (int i = t; i < 8192; i += 512) {
        float4 v = xp[i];
        s  += v.x + v.y + v.z + v.w;
        s2 += v.x * v.x + v.y * v.y + v.z * v.z + v.w * v.w;
    }
    __shared__ float r1[512], r2[512];
    r1[t] = s; r2[t] = s2;
    __syncthreads();
    for (int st = 256; st > 0; st >>= 1) {
        if (t < st) { r1[t] += r1[t + st]; r2[t] += r2[t + st]; }
        __syncthreads();
    }
    float mean = r1[0] * (1.f / 32768.f);
    float var  = r2[0] * (1.f / 32768.f) - mean * mean;
    float inv  = rsqrtf(var + 1e-5f);

    for (int i = t; i < 8192; i += 512) {
        int c = g * 32 + (i >> 8);       // 256 float4 per channel
        float a = inv * sc[c];
        float b = bi[c] - mean * a;
        float4 v = xp[i];
        v.x = v.x * a + b; v.y = v.y * a + b;
        v.z = v.z * a + b; v.w = v.w * a + b;
        hp[i] = v;
    }
}

// ---------------------------------------------------------------------------
// Kernel 2/4: batched SGEMM  out[b][m][n] = sum_c W[m][c]*src[b][c][n] + bias[m]
// (+ optional residual). Block tile 64x64, K tile 16, 4x4 per thread, FFMA2.
// grid: (N/64, M/64, B), block: 256.
// ---------------------------------------------------------------------------
__global__ void gemm_kernel(const float* __restrict__ W,
                            const float* __restrict__ bias,
                            const float* __restrict__ src,
                            const float* __restrict__ resid,
                            float* __restrict__ out, int M) {
    int b  = blockIdx.z;
    const float* Bp = src + (size_t)b * CCH * NSP;
    int m0 = blockIdx.y * 64, n0 = blockIdx.x * 64;

    __shared__ float As[16][64];   // [k][m]
    __shared__ float Bs[16][64];   // [k][n]

    int tid = threadIdx.x;
    int tx = tid & 15, ty = tid >> 4;

    int wm = tid >> 2;            // 0..63  (m)
    int wk = (tid & 3) * 4;       // 0,4,8,12
    int bk = tid >> 4;            // 0..15  (k)
    int bn = (tid & 15) * 4;      // n

    ULL acc[4][2] = {};           // 4 m-rows x 2 packed n-pairs

    for (int k0 = 0; k0 < CCH; k0 += 16) {
        float4 wv = *(const float4*)&W[(size_t)(m0 + wm) * CCH + k0 + wk];
        float4 bv = *(const float4*)&Bp[(size_t)(k0 + bk) * NSP + n0 + bn];
        As[wk + 0][wm] = wv.x;
        As[wk + 1][wm] = wv.y;
        As[wk + 2][wm] = wv.z;
        As[wk + 3][wm] = wv.w;
        *(float4*)&Bs[bk][bn] = bv;
        __syncthreads();

        #pragma unroll
        for (int kk = 0; kk < 16; kk++) {
            float4 a = *(const float4*)&As[kk][ty * 4];
            ulonglong2 bb = *(const ulonglong2*)&Bs[kk][tx * 4];
            ULL a0 = dup2(a.x), a1 = dup2(a.y), a2 = dup2(a.z), a3 = dup2(a.w);
            acc[0][0] = ffma2(a0, bb.x, acc[0][0]); acc[0][1] = ffma2(a0, bb.y, acc[0][1]);
            acc[1][0] = ffma2(a1, bb.x, acc[1][0]); acc[1][1] = ffma2(a1, bb.y, acc[1][1]);
            acc[2][0] = ffma2(a2, bb.x, acc[2][0]); acc[2][1] = ffma2(a2, bb.y, acc[2][1]);
            acc[3][0] = ffma2(a3, bb.x, acc[3][0]); acc[3][1] = ffma2(a3, bb.y, acc[3][1]);
        }
        __syncthreads();
    }

    #pragma unroll
    for (int i = 0; i < 4; i++) {
        int m = m0 + ty * 4 + i;
        float bsv = bias[m];
        size_t base = (size_t)b * M * NSP + (size_t)m * NSP + n0 + tx * 4;
        float2 lo = upk2(acc[i][0]), hi = upk2(acc[i][1]);
        float4 o;
        o.x = lo.x + bsv; o.y = lo.y + bsv;
        o.z = hi.x + bsv; o.w = hi.y + bsv;
        if (resid) {
            float4 r = *(const float4*)&resid[base];
            o.x += r.x; o.y += r.y; o.z += r.z; o.w += r.w;
        }
        *(float4*)&out[base] = o;
    }
}

// ---------------------------------------------------------------------------
// Kernel 3: attention. One block per (b, head, 64-query tile).
// Flash-style online softmax over 16 K/V tiles of 64. FFMA2 everywhere.
//  S phase:  16x16 threads, 4q x 4k registers (packed pairs along k).
//  PV phase: 32x8 threads, 2q x 4d registers (packed pairs along d), V stored
//            transposed (Vt[m][d]) so shared reads are 64/128-bit.
// grid: 1024 blocks, 256 threads.
// ---------------------------------------------------------------------------
__global__ void attn_kernel() {
    int blk = blockIdx.x;
    int qt  = blk & 15;          // query tile
    int bh  = blk >> 4;          // b*8 + h
    const float* qb = g_qkv + (size_t)(bh >> 3) * 3 * CCH * NSP
                            + (size_t)((bh & 7) * HD) * NSP;
    const float* kb = qb + (size_t)CCH * NSP;
    const float* vb = kb + (size_t)CCH * NSP;
    int n0 = qt * 64;

    __shared__ float Qs[32][68];     // [d][q], rows 16B-aligned
    __shared__ float Ks[32][68];     // [d][m]
    __shared__ float Vt[64][34];     // [m][d], rows 8B-aligned
    __shared__ float Ss[64][68];     // P tile [q][m]; reused as O staging [q][d]
    __shared__ float row_corr[64], row_sum[64];

    int tid = threadIdx.x;
    const float scale = 0.17677669529663687f;  // 1/sqrt(32)

    // Load Q tile [32 dims][64 queries], pre-scaled
    for (int i = tid; i < 2048; i += 256) {
        int d = i >> 6, q = i & 63;
        Qs[d][q] = qb[d * NSP + n0 + q] * scale;
    }

    int tx  = tid & 15, ty  = tid >> 4;   // S phase
    int tx2 = tid & 7,  ty2 = tid >> 3;   // PV phase
    int q0   = ty2 * 2;
    int dcol = tx2 * 4;

    float m_i[4], l_i[4];
    #pragma unroll
    for (int r = 0; r < 4; r++) { m_i[r] = -1e30f; l_i[r] = 0.f; }
    ULL accp[2][2] = {};                  // [2 q][2 packed d-pairs]

    for (int kt = 0; kt < 16; kt++) {
        __syncthreads();   // protect Ks/Vt/Ss from previous iteration readers
        int m0 = kt * 64;
        for (int i = tid; i < 2048; i += 256) {
            int d = i >> 6, m = i & 63;
            float kv = kb[d * NSP + m0 + m];
            float vv = vb[d * NSP + m0 + m];
            Ks[d][m] = kv;
            Vt[m][d] = vv;
        }
        __syncthreads();

        // ---- S = (Q*scale)^T K : 4x4 per thread, packed along k ----
        ULL s2[4][2] = {};
        #pragma unroll
        for (int d = 0; d < 32; d++) {
            float4 qa = *(const float4*)&Qs[d][ty * 4];
            ulonglong2 kv = *(const ulonglong2*)&Ks[d][tx * 4];
            ULL a0 = dup2(qa.x), a1 = dup2(qa.y), a2 = dup2(qa.z), a3 = dup2(qa.w);
            s2[0][0] = ffma2(a0, kv.x, s2[0][0]); s2[0][1] = ffma2(a0, kv.y, s2[0][1]);
            s2[1][0] = ffma2(a1, kv.x, s2[1][0]); s2[1][1] = ffma2(a1, kv.y, s2[1][1]);
            s2[2][0] = ffma2(a2, kv.x, s2[2][0]); s2[2][1] = ffma2(a2, kv.y, s2[2][1]);
            s2[3][0] = ffma2(a3, kv.x, s2[3][0]); s2[3][1] = ffma2(a3, kv.y, s2[3][1]);
        }

        // ---- online softmax in registers; 16 lanes own each row ----
        #pragma unroll
        for (int r = 0; r < 4; r++) {
            float2 v01 = upk2(s2[r][0]);
            float2 v23 = upk2(s2[r][1]);
            float mx = fmaxf(fmaxf(v01.x, v01.y), fmaxf(v23.x, v23.y));
            mx = fmaxf(mx, __shfl_xor_sync(0xffffffffu, mx, 1));
            mx = fmaxf(mx, __shfl_xor_sync(0xffffffffu, mx, 2));
            mx = fmaxf(mx, __shfl_xor_sync(0xffffffffu, mx, 4));
            mx = fmaxf(mx, __shfl_xor_sync(0xffffffffu, mx, 8));
            float m_new = fmaxf(m_i[r], mx);
            float corr  = __expf(m_i[r] - m_new);
            float p0 = __expf(v01.x - m_new);
            float p1 = __expf(v01.y - m_new);
            float p2 = __expf(v23.x - m_new);
            float p3 = __expf(v23.y - m_new);
            *(float4*)&Ss[ty * 4 + r][tx * 4] = make_float4(p0, p1, p2, p3);
            float ls = p0 + p1 + p2 + p3;
            ls += __shfl_xor_sync(0xffffffffu, ls, 1);
            ls += __shfl_xor_sync(0xffffffffu, ls, 2);
            ls += __shfl_xor_sync(0xffffffffu, ls, 4);
            ls += __shfl_xor_sync(0xffffffffu, ls, 8);
            l_i[r] = l_i[r] * corr + ls;
            m_i[r] = m_new;
            if (tx == 0) row_corr[ty * 4 + r] = corr;
        }
        __syncthreads();

        // ---- O = O*corr + P @ V^T : 2q x 4d per thread, packed along d ----
        ULL c0 = dup2(row_corr[q0]);
        ULL c1 = dup2(row_corr[q0 + 1]);
        accp[0][0] = fmul2(accp[0][0], c0); accp[0][1] = fmul2(accp[0][1], c0);
        accp[1][0] = fmul2(accp[1][0], c1); accp[1][1] = fmul2(accp[1][1], c1);

        #pragma unroll 4
        for (int m = 0; m < 64; m += 4) {
            float4 pa = *(const float4*)&Ss[q0][m];
            float4 pb = *(const float4*)&Ss[q0 + 1][m];
            #pragma unroll
            for (int k = 0; k < 4; k++) {
                const ULL* vr = (const ULL*)&Vt[m + k][dcol];
                ULL v01 = vr[0], v23 = vr[1];
                float pav = (k == 0) ? pa.x : (k == 1) ? pa.y : (k == 2) ? pa.z : pa.w;
                float pbv = (k == 0) ? pb.x : (k == 1) ? pb.y : (k == 2) ? pb.z : pb.w;
                ULL d0 = dup2(pav), d1 = dup2(pbv);
                accp[0][0] = ffma2(d0, v01, accp[0][0]);
                accp[0][1] = ffma2(d0, v23, accp[0][1]);
                accp[1][0] = ffma2(d1, v01, accp[1][0]);
                accp[1][1] = ffma2(d1, v23, accp[1][1]);
            }
        }
    }

    // ---- epilogue: normalize, stage O in smem, coalesced store ----
    #pragma unroll
    for (int r = 0; r < 4; r++)
        if (tx == 0) row_sum[ty * 4 + r] = l_i[r];
    __syncthreads();

    float inv0 = 1.f / row_sum[q0];
    float inv1 = 1.f / row_sum[q0 + 1];
    {
        float2 a = upk2(accp[0][0]), b = upk2(accp[0][1]);
        Ss[q0][dcol + 0] = a.x * inv0; Ss[q0][dcol + 1] = a.y * inv0;
        Ss[q0][dcol + 2] = b.x * inv0; Ss[q0][dcol + 3] = b.y * inv0;
        float2 c = upk2(accp[1][0]), d = upk2(accp[1][1]);
        Ss[q0 + 1][dcol + 0] = c.x * inv1; Ss[q0 + 1][dcol + 1] = c.y * inv1;
        Ss[q0 + 1][dcol + 2] = d.x * inv1; Ss[q0 + 1][dcol + 3] = d.y * inv1;
    }
    __syncthreads();

    float* op = g_att + (size_t)bh * HD * NSP;
    for (int i = tid; i < 2048; i += 256) {
        int d = i >> 6, q = i & 63;
        op[(size_t)d * NSP + n0 + q] = Ss[q][d];
    }
}

// ---------------------------------------------------------------------------
extern "C" void kernel_launch(void* const* d_in, const int* in_sizes, int n_in,
                              void* d_out, int out_size) {
    const float* x        = (const float*)d_in[0];
    const float* gn_scale = (const float*)d_in[1];
    const float* gn_bias  = (const float*)d_in[2];
    const float* w_qkv    = (const float*)d_in[3];
    const float* b_qkv    = (const float*)d_in[4];
    const float* w_out    = (const float*)d_in[5];
    const float* b_out    = (const float*)d_in[6];
    float* out = (float*)d_out;

    float *ph, *pqkv, *patt;
    cudaGetSymbolAddress((void**)&ph,   g_h);
    cudaGetSymbolAddress((void**)&pqkv, g_qkv);
    cudaGetSymbolAddress((void**)&patt, g_att);

    // 1. GroupNorm
    gn_kernel<<<BATCH * 8, 512>>>(x, gn_scale, gn_bias);
    // 2. QKV projection: [768,256] @ [256,1024] per batch
    gemm_kernel<<<dim3(16, 12, BATCH), 256>>>(w_qkv, b_qkv, ph, nullptr, pqkv, 768);
    // 3. Attention
    attn_kernel<<<BATCH * HEADS * 16, 256>>>();
    // 4. Output projection + residual
    gemm_kernel<<<dim3(16, 4, BATCH), 256>>>(w_out, b_out, patt, x, out, 256);
}

// round 3
// speedup vs baseline: 1.5201x; 1.0360x over previous
#include <cuda_runtime.h>

// Problem constants: B=8, C=256, H=W=32 -> N=1024, heads=8, hd=32, groups=8.
#define BATCH   8
#define CCH     256
#define NSP     1024
#define HEADS   8
#define HD      32

typedef unsigned long long ULL;

// ---- packed f32x2 helpers (sm_103a FFMA2 path, PTX-only) -------------------
__device__ __forceinline__ ULL pk2(float lo, float hi) {
    ULL r; asm("mov.b64 %0, {%1,%2};" : "=l"(r) : "f"(lo), "f"(hi)); return r;
}
__device__ __forceinline__ float2 upk2(ULL v) {
    float2 f; asm("mov.b64 {%0,%1}, %2;" : "=f"(f.x), "=f"(f.y) : "l"(v)); return f;
}
__device__ __forceinline__ ULL dup2(float x) { return pk2(x, x); }
__device__ __forceinline__ ULL ffma2(ULL a, ULL b, ULL c) {
    ULL d; asm("fma.rn.f32x2 %0, %1, %2, %3;" : "=l"(d) : "l"(a), "l"(b), "l"(c));
    return d;
}
__device__ __forceinline__ ULL fmul2(ULL a, ULL b) {
    ULL d; asm("mul.rn.f32x2 %0, %1, %2;" : "=l"(d) : "l"(a), "l"(b)); return d;
}
__device__ __forceinline__ float ex2(float x) {
    float y; asm("ex2.approx.ftz.f32 %0, %1;" : "=f"(y) : "f"(x)); return y;
}

// Scratch (device globals; no allocation APIs allowed)
__device__ float g_qkv[BATCH * 3 * CCH * NSP];  // qkv              [b][o][n]
__device__ float g_att[BATCH * CCH * NSP];      // attention output [b][c][n]
__device__ float g_sA[BATCH * CCH];             // GN fused affine scale per (b,c)
__device__ float g_sB[BATCH * CCH];             // GN fused affine shift per (b,c)

// ---------------------------------------------------------------------------
// Kernel 1: GroupNorm statistics only. One block per (b, group).
// Emits per-channel affine (a, b) such that xnorm = x*a + b.
// ---------------------------------------------------------------------------
__global__ void gn_stats_kernel(const float* __restrict__ x,
                                const float* __restrict__ sc,
                                const float* __restrict__ bi) {
    int bg = blockIdx.x;            // b*8 + g
    int g  = bg & 7;
    const float4* xp = (const float4*)(x + (size_t)bg * 32 * NSP);

    int t = threadIdx.x;
    float s = 0.f, s2 = 0.f;
    for (int i = t; i < 8192; i += 256) {
        float4 v = xp[i];
        s  += v.x + v.y + v.z + v.w;
        s2 += v.x * v.x + v.y * v.y + v.z * v.z + v.w * v.w;
    }
    __shared__ float r1[256], r2[256];
    r1[t] = s; r2[t] = s2;
    __syncthreads();
    for (int st = 128; st > 0; st >>= 1) {
        if (t < st) { r1[t] += r1[t + st]; r2[t] += r2[t + st]; }
        __syncthreads();
    }
    float mean = r1[0] * (1.f / 32768.f);
    float var  = r2[0] * (1.f / 32768.f) - mean * mean;
    float inv  = rsqrtf(var + 1e-5f);

    if (t < 32) {
        int c = g * 32 + t;
        float a = inv * sc[c];
        g_sA[(bg >> 3) * CCH + c] = a;
        g_sB[(bg >> 3) * CCH + c] = bi[c] - mean * a;
    }
}

// ---------------------------------------------------------------------------
// Kernel 2/4: batched SGEMM  out[b][m][n] = sum_c W[m][c]*f(src[b][c][n]) + bias[m]
// f = optional per-(b,c) affine (fused GroupNorm), optional residual add.
// Block tile 64x64, K tile 16, 4x4 per thread, FFMA2, double-buffered smem.
// grid: (N/64, M/64, B), block: 256.
// ---------------------------------------------------------------------------
__global__ void __launch_bounds__(256)
gemm_kernel(const float* __restrict__ W,
            const float* __restrict__ bias,
            const float* __restrict__ src,
            const float* __restrict__ resid,
            float* __restrict__ out, int M,
            const float* __restrict__ gA,
            const float* __restrict__ gB) {
    int b  = blockIdx.z;
    const float* Bp = src + (size_t)b * CCH * NSP;
    int m0 = blockIdx.y * 64, n0 = blockIdx.x * 64;

    __shared__ float As[2][16][64];   // [buf][k][m]
    __shared__ float Bs[2][16][64];   // [buf][k][n]

    int tid = threadIdx.x;
    int tx = tid & 15, ty = tid >> 4;

    int wm = tid >> 2;            // 0..63  (m)
    int wk = (tid & 3) * 4;       // 0,4,8,12
    int bk = tid >> 4;            // 0..15  (k)
    int bn = (tid & 15) * 4;      // n

    ULL acc[4][2] = {};           // 4 m-rows x 2 packed n-pairs

    // prologue: k-tile 0 into registers
    float4 wv = *(const float4*)&W[(size_t)(m0 + wm) * CCH + wk];
    float4 bv = *(const float4*)&Bp[(size_t)bk * NSP + n0 + bn];
    if (gA) {
        float a = gA[b * CCH + bk], s = gB[b * CCH + bk];
        bv.x = bv.x * a + s; bv.y = bv.y * a + s;
        bv.z = bv.z * a + s; bv.w = bv.w * a + s;
    }

    int buf = 0;
    for (int k0 = 0; k0 < CCH; k0 += 16) {
        As[buf][wk + 0][wm] = wv.x;
        As[buf][wk + 1][wm] = wv.y;
        As[buf][wk + 2][wm] = wv.z;
        As[buf][wk + 3][wm] = wv.w;
        *(float4*)&Bs[buf][bk][bn] = bv;
        __syncthreads();

        if (k0 + 16 < CCH) {   // prefetch next tile (latency hidden by compute)
            int kn = k0 + 16;
            wv = *(const float4*)&W[(size_t)(m0 + wm) * CCH + kn + wk];
            bv = *(const float4*)&Bp[(size_t)(kn + bk) * NSP + n0 + bn];
            if (gA) {
                float a = gA[b * CCH + kn + bk], s = gB[b * CCH + kn + bk];
                bv.x = bv.x * a + s; bv.y = bv.y * a + s;
                bv.z = bv.z * a + s; bv.w = bv.w * a + s;
            }
        }

        #pragma unroll
        for (int kk = 0; kk < 16; kk++) {
            float4 a = *(const float4*)&As[buf][kk][ty * 4];
            ulonglong2 bb = *(const ulonglong2*)&Bs[buf][kk][tx * 4];
            ULL a0 = dup2(a.x), a1 = dup2(a.y), a2 = dup2(a.z), a3 = dup2(a.w);
            acc[0][0] = ffma2(a0, bb.x, acc[0][0]); acc[0][1] = ffma2(a0, bb.y, acc[0][1]);
            acc[1][0] = ffma2(a1, bb.x, acc[1][0]); acc[1][1] = ffma2(a1, bb.y, acc[1][1]);
            acc[2][0] = ffma2(a2, bb.x, acc[2][0]); acc[2][1] = ffma2(a2, bb.y, acc[2][1]);
            acc[3][0] = ffma2(a3, bb.x, acc[3][0]); acc[3][1] = ffma2(a3, bb.y, acc[3][1]);
        }
        buf ^= 1;
    }

    #pragma unroll
    for (int i = 0; i < 4; i++) {
        int m = m0 + ty * 4 + i;
        float bsv = bias[m];
        size_t base = (size_t)b * M * NSP + (size_t)m * NSP + n0 + tx * 4;
        float2 lo = upk2(acc[i][0]), hi = upk2(acc[i][1]);
        float4 o;
        o.x = lo.x + bsv; o.y = lo.y + bsv;
        o.z = hi.x + bsv; o.w = hi.y + bsv;
        if (resid) {
            float4 r = *(const float4*)&resid[base];
            o.x += r.x; o.y += r.y; o.z += r.z; o.w += r.w;
        }
        *(float4*)&out[base] = o;
    }
}

// ---------------------------------------------------------------------------
// Kernel 3: attention. One block per (b, head, 64-query tile).
// KT=128 key tile, 8 iterations, register-prefetched K/V, V double-buffered,
// 2 barriers/iter. Base-2 online softmax (log2e folded into Q scale).
//  S phase:  16x16 threads, 4q x 8k (packed pairs along k).
//  PV phase: 32x8 threads, 2q x 4d (packed pairs along d), V transposed.
// Dynamic smem: 96768 bytes.
// ---------------------------------------------------------------------------
#define ATTN_SMEM_BYTES 96768
// float offsets within dynamic smem:
//  Qs  [32][68]     @ 0      (2176)
//  Ks  [32][132]    @ 2176   (4224)
//  Vt  [2][128][36] @ 6400   (9216)
//  Ss  [64][132]    @ 15616  (8448)
//  rowc[64]         @ 24064
//  rows[64]         @ 24128

__global__ void __launch_bounds__(256, 2) attn_kernel() {
    extern __shared__ float sm[];
    float* Qs   = sm;
    float* Ks   = sm + 2176;
    float* Vt   = sm + 6400;     // two buffers of 128*36 = 4608
    float* Ss   = sm + 15616;
    float* rowc = sm + 24064;
    float* rows = sm + 24128;

    int blk = blockIdx.x;
    int qt  = blk & 15;          // query tile
    int bh  = blk >> 4;          // b*8 + h
    const float* qb = g_qkv + (size_t)(bh >> 3) * 3 * CCH * NSP
                            + (size_t)((bh & 7) * HD) * NSP;
    const float* kb = qb + (size_t)CCH * NSP;
    const float* vb = kb + (size_t)CCH * NSP;
    int n0 = qt * 64;

    int tid = threadIdx.x;
    // scale * log2(e): softmax done in base 2 with a single EX2 per score
    const float qscale = 0.17677669529663687f * 1.4426950408889634f;

    // Load Q tile [32 dims][64 queries], pre-scaled
    for (int i = tid; i < 2048; i += 256) {
        int d = i >> 6, q = i & 63;
        Qs[d * 68 + q] = qb[d * NSP + n0 + q] * qscale;
    }

    // K load mapping: 4 chunks of float4; V load mapping: transposed scalars
    int vm  = tid & 127;          // key index within tile
    int vd0 = (tid >> 7) * 16;    // dim group base (0 or 16)

    // ---- prologue: tile 0 directly into smem ----
    #pragma unroll
    for (int c = 0; c < 4; c++) {
        int idx = c * 256 + tid, d = idx >> 5, mq = (idx & 31) * 4;
        float4 kv = *(const float4*)&kb[d * NSP + mq];
        *(float4*)&Ks[d * 132 + mq] = kv;
    }
    #pragma unroll
    for (int c = 0; c < 4; c++) {
        int d = vd0 + c * 4;
        float4 vv;
        vv.x = vb[(d + 0) * NSP + vm];
        vv.y = vb[(d + 1) * NSP + vm];
        vv.z = vb[(d + 2) * NSP + vm];
        vv.w = vb[(d + 3) * NSP + vm];
        *(float4*)&Vt[vm * 36 + d] = vv;   // buffer 0
    }
    __syncthreads();

    int tx  = tid & 15, ty  = tid >> 4;   // S phase
    int tx2 = tid & 7,  ty2 = tid >> 3;   // PV phase
    int q0   = ty2 * 2;
    int dcol = tx2 * 4;

    float m_i[4], l_i[4];
    #pragma unroll
    for (int r = 0; r < 4; r++) { m_i[r] = -1e30f; l_i[r] = 0.f; }
    ULL accp[2][2] = {};                  // [2 q][2 packed d-pairs]

    float4 kreg[4];
    float  vreg[4][4];

    for (int kt = 0; kt < 8; kt++) {
        int buf = kt & 1;
        bool more = (kt + 1 < 8);

        // ---- prefetch next K/V tile into registers (in flight during S) ----
        if (more) {
            int m0n = (kt + 1) * 128;
            #pragma unroll
            for (int c = 0; c < 4; c++) {
                int idx = c * 256 + tid, d = idx >> 5, mq = (idx & 31) * 4;
                kreg[c] = *(const float4*)&kb[d * NSP + m0n + mq];
            }
            #pragma unroll
            for (int c = 0; c < 4; c++) {
                int d = vd0 + c * 4;
                vreg[c][0] = vb[(d + 0) * NSP + m0n + vm];
                vreg[c][1] = vb[(d + 1) * NSP + m0n + vm];
                vreg[c][2] = vb[(d + 2) * NSP + m0n + vm];
                vreg[c][3] = vb[(d + 3) * NSP + m0n + vm];
            }
        }

        // ---- S = (Q*scale)^T K : 4q x 8k per thread, packed along k ----
        ULL s2[4][4] = {};
        #pragma unroll
        for (int d = 0; d < 32; d++) {
            float4 qa = *(const float4*)&Qs[d * 68 + ty * 4];
            ulonglong2 ka = *(const ulonglong2*)&Ks[d * 132 + tx * 4];
            ulonglong2 kc = *(const ulonglong2*)&Ks[d * 132 + 64 + tx * 4];
            ULL a0 = dup2(qa.x), a1 = dup2(qa.y), a2 = dup2(qa.z), a3 = dup2(qa.w);
            s2[0][0] = ffma2(a0, ka.x, s2[0][0]); s2[0][1] = ffma2(a0, ka.y, s2[0][1]);
            s2[0][2] = ffma2(a0, kc.x, s2[0][2]); s2[0][3] = ffma2(a0, kc.y, s2[0][3]);
            s2[1][0] = ffma2(a1, ka.x, s2[1][0]); s2[1][1] = ffma2(a1, ka.y, s2[1][1]);
            s2[1][2] = ffma2(a1, kc.x, s2[1][2]); s2[1][3] = ffma2(a1, kc.y, s2[1][3]);
            s2[2][0] = ffma2(a2, ka.x, s2[2][0]); s2[2][1] = ffma2(a2, ka.y, s2[2][1]);
            s2[2][2] = ffma2(a2, kc.x, s2[2][2]); s2[2][3] = ffma2(a2, kc.y, s2[2][3]);
            s2[3][0] = ffma2(a3, ka.x, s2[3][0]); s2[3][1] = ffma2(a3, ka.y, s2[3][1]);
            s2[3][2] = ffma2(a3, kc.x, s2[3][2]); s2[3][3] = ffma2(a3, kc.y, s2[3][3]);
        }

        // ---- online softmax (base 2) in registers; 16 lanes per row ----
        #pragma unroll
        for (int r = 0; r < 4; r++) {
            float2 a0 = upk2(s2[r][0]), a1 = upk2(s2[r][1]);
            float2 a2 = upk2(s2[r][2]), a3 = upk2(s2[r][3]);
            float mx = fmaxf(fmaxf(fmaxf(a0.x, a0.y), fmaxf(a1.x, a1.y)),
                             fmaxf(fmaxf(a2.x, a2.y), fmaxf(a3.x, a3.y)));
            mx = fmaxf(mx, __shfl_xor_sync(0xffffffffu, mx, 1));
            mx = fmaxf(mx, __shfl_xor_sync(0xffffffffu, mx, 2));
            mx = fmaxf(mx, __shfl_xor_sync(0xffffffffu, mx, 4));
            mx = fmaxf(mx, __shfl_xor_sync(0xffffffffu, mx, 8));
            float m_new = fmaxf(m_i[r], mx);
            float corr  = ex2(m_i[r] - m_new);
            float p0 = ex2(a0.x - m_new), p1 = ex2(a0.y - m_new);
            float p2 = ex2(a1.x - m_new), p3 = ex2(a1.y - m_new);
            float p4 = ex2(a2.x - m_new), p5 = ex2(a2.y - m_new);
            float p6 = ex2(a3.x - m_new), p7 = ex2(a3.y - m_new);
            int row = ty * 4 + r;
            *(float4*)&Ss[row * 132 + tx * 4]      = make_float4(p0, p1, p2, p3);
            *(float4*)&Ss[row * 132 + 64 + tx * 4] = make_float4(p4, p5, p6, p7);
            float ls = ((p0 + p1) + (p2 + p3)) + ((p4 + p5) + (p6 + p7));
            ls += __shfl_xor_sync(0xffffffffu, ls, 1);
            ls += __shfl_xor_sync(0xffffffffu, ls, 2);
            ls += __shfl_xor_sync(0xffffffffu, ls, 4);
            ls += __shfl_xor_sync(0xffffffffu, ls, 8);
            l_i[r] = l_i[r] * corr + ls;
            m_i[r] = m_new;
            if (tx == 0) rowc[row] = corr;
        }
        __syncthreads();   // (A): P visible; S-phase done reading Ks; prev PV done

        // ---- drain prefetch: K overwrites Ks, V goes to other buffer ----
        if (more) {
            #pragma unroll
            for (int c = 0; c < 4; c++) {
                int idx = c * 256 + tid, d = idx >> 5, mq = (idx & 31) * 4;
                *(float4*)&Ks[d * 132 + mq] = kreg[c];
            }
            float* Vo = Vt + (buf ^ 1) * 4608;
            #pragma unroll
            for (int c = 0; c < 4; c++) {
                int d = vd0 + c * 4;
                *(float4*)&Vo[vm * 36 + d] =
                    make_float4(vreg[c][0], vreg[c][1], vreg[c][2], vreg[c][3]);
            }
        }

        // ---- O = O*corr + P @ V^T : 2q x 4d per thread, packed along d ----
        ULL c0 = dup2(rowc[q0]);
        ULL c1 = dup2(rowc[q0 + 1]);
        accp[0][0] = fmul2(accp[0][0], c0); accp[0][1] = fmul2(accp[0][1], c0);
        accp[1][0] = fmul2(accp[1][0], c1); accp[1][1] = fmul2(accp[1][1], c1);

        const float* Vb = Vt + buf * 4608;
        #pragma unroll 4
        for (int m = 0; m < 128; m += 4) {
            float4 pa = *(const float4*)&Ss[q0 * 132 + m];
            float4 pb = *(const float4*)&Ss[(q0 + 1) * 132 + m];
            #pragma unroll
            for (int k = 0; k < 4; k++) {
                const ULL* vr = (const ULL*)&Vb[(m + k) * 36 + dcol];
                ULL v01 = vr[0], v23 = vr[1];
                float pav = (k == 0) ? pa.x : (k == 1) ? pa.y : (k == 2) ? pa.z : pa.w;
                float pbv = (k == 0) ? pb.x : (k == 1) ? pb.y : (k == 2) ? pb.z : pb.w;
                ULL d0 = dup2(pav), d1 = dup2(pbv);
                accp[0][0] = ffma2(d0, v01, accp[0][0]);
                accp[0][1] = ffma2(d0, v23, accp[0][1]);
                accp[1][0] = ffma2(d1, v01, accp[1][0]);
                accp[1][1] = ffma2(d1, v23, accp[1][1]);
            }
        }
        __syncthreads();   // (B): stores visible for next S; Vt[buf] free
    }

    // ---- epilogue: normalize, stage O in smem, coalesced store ----
    #pragma unroll
    for (int r = 0; r < 4; r++)
        if (tx == 0) rows[ty * 4 + r] = l_i[r];
    __syncthreads();

    float inv0 = 1.f / rows[q0];
    float inv1 = 1.f / rows[q0 + 1];
    {
        float2 a = upk2(accp[0][0]), b = upk2(accp[0][1]);
        Ss[q0 * 132 + dcol + 0] = a.x * inv0; Ss[q0 * 132 + dcol + 1] = a.y * inv0;
        Ss[q0 * 132 + dcol + 2] = b.x * inv0; Ss[q0 * 132 + dcol + 3] = b.y * inv0;
        float2 c = upk2(accp[1][0]), d = upk2(accp[1][1]);
        Ss[(q0 + 1) * 132 + dcol + 0] = c.x * inv1; Ss[(q0 + 1) * 132 + dcol + 1] = c.y * inv1;
        Ss[(q0 + 1) * 132 + dcol + 2] = d.x * inv1; Ss[(q0 + 1) * 132 + dcol + 3] = d.y * inv1;
    }
    __syncthreads();

    float* op = g_att + (size_t)bh * HD * NSP;
    for (int i = tid; i < 2048; i += 256) {
        int d = i >> 6, q = i & 63;
        op[(size_t)d * NSP + n0 + q] = Ss[q * 132 + d];
    }
}

// ---------------------------------------------------------------------------
extern "C" void kernel_launch(void* const* d_in, const int* in_sizes, int n_in,
                              void* d_out, int out_size) {
    const float* x        = (const float*)d_in[0];
    const float* gn_scale = (const float*)d_in[1];
    const float* gn_bias  = (const float*)d_in[2];
    const float* w_qkv    = (const float*)d_in[3];
    const float* b_qkv    = (const float*)d_in[4];
    const float* w_out    = (const float*)d_in[5];
    const float* b_out    = (const float*)d_in[6];
    float* out = (float*)d_out;

    float *pqkv, *patt, *psA, *psB;
    cudaGetSymbolAddress((void**)&pqkv, g_qkv);
    cudaGetSymbolAddress((void**)&patt, g_att);
    cudaGetSymbolAddress((void**)&psA,  g_sA);
    cudaGetSymbolAddress((void**)&psB,  g_sB);

    cudaFuncSetAttribute(attn_kernel,
                         cudaFuncAttributeMaxDynamicSharedMemorySize,
                         ATTN_SMEM_BYTES);

    // 1. GroupNorm statistics (affine folded into QKV GEMM loads)
    gn_stats_kernel<<<BATCH * 8, 256>>>(x, gn_scale, gn_bias);
    // 2. QKV projection with fused GroupNorm: [768,256] @ [256,1024] per batch
    gemm_kernel<<<dim3(16, 12, BATCH), 256>>>(w_qkv, b_qkv, x, nullptr, pqkv,
                                              768, psA, psB);
    // 3. Attention
    attn_kernel<<<BATCH * HEADS * 16, 256, ATTN_SMEM_BYTES>>>();
    // 4. Output projection + residual
    gemm_kernel<<<dim3(16, 4, BATCH), 256>>>(w_out, b_out, patt, x, out,
                                             256, nullptr, nullptr);
}

// round 4
// speedup vs baseline: 2.7755x; 1.8259x over previous
#include <cuda_runtime.h>

// Problem constants: B=8, C=256, H=W=32 -> N=1024, heads=8, hd=32, groups=8.
#define BATCH   8
#define CCH     256
#define NSP     1024
#define HEADS   8
#define HD      32

// ---- helpers ---------------------------------------------------------------
__device__ __forceinline__ float tf32r(float x) {
    unsigned u; asm("cvt.rna.tf32.f32 %0, %1;" : "=r"(u) : "f"(x));
    return __uint_as_float(u);
}
__device__ __forceinline__ unsigned fu(float x) { return __float_as_uint(x); }
__device__ __forceinline__ float ex2(float x) {
    float y; asm("ex2.approx.ftz.f32 %0, %1;" : "=f"(y) : "f"(x)); return y;
}
// D += A(16x8, tf32 row) * B(8x8, tf32 col), fp32 accumulate
__device__ __forceinline__ void mma_tf32(float4& d, unsigned a0, unsigned a1,
                                         unsigned a2, unsigned a3,
                                         unsigned b0, unsigned b1) {
    asm("mma.sync.aligned.m16n8k8.row.col.f32.tf32.tf32.f32 "
        "{%0,%1,%2,%3},{%4,%5,%6,%7},{%8,%9},{%0,%1,%2,%3};"
        : "+f"(d.x), "+f"(d.y), "+f"(d.z), "+f"(d.w)
        : "r"(a0), "r"(a1), "r"(a2), "r"(a3), "r"(b0), "r"(b1));
}

// Scratch (device globals; no allocation APIs allowed)
__device__ float g_qkv[BATCH * 3 * CCH * NSP];  // qkv              [b][o][n]
__device__ float g_att[BATCH * CCH * NSP];      // attention output [b][c][n]
__device__ float g_sA[BATCH * CCH];             // GN fused affine scale per (b,c)
__device__ float g_sB[BATCH * CCH];             // GN fused affine shift per (b,c)

// ---------------------------------------------------------------------------
// Kernel 1: GroupNorm statistics only. One block per (b, group).
// ---------------------------------------------------------------------------
__global__ void gn_stats_kernel(const float* __restrict__ x,
                                const float* __restrict__ sc,
                                const float* __restrict__ bi) {
    int bg = blockIdx.x;            // b*8 + g
    int g  = bg & 7;
    const float4* xp = (const float4*)(x + (size_t)bg * 32 * NSP);

    int t = threadIdx.x;
    float s = 0.f, s2 = 0.f;
    for (int i = t; i < 8192; i += 256) {
        float4 v = xp[i];
        s  += v.x + v.y + v.z + v.w;
        s2 += v.x * v.x + v.y * v.y + v.z * v.z + v.w * v.w;
    }
    __shared__ float r1[256], r2[256];
    r1[t] = s; r2[t] = s2;
    __syncthreads();
    for (int st = 128; st > 0; st >>= 1) {
        if (t < st) { r1[t] += r1[t + st]; r2[t] += r2[t + st]; }
        __syncthreads();
    }
    float mean = r1[0] * (1.f / 32768.f);
    float var  = r2[0] * (1.f / 32768.f) - mean * mean;
    float inv  = rsqrtf(var + 1e-5f);

    if (t < 32) {
        int c = g * 32 + t;
        float a = inv * sc[c];
        g_sA[(bg >> 3) * CCH + c] = a;
        g_sB[(bg >> 3) * CCH + c] = bi[c] - mean * a;
    }
}

// ---------------------------------------------------------------------------
// Kernel 2/4: batched GEMM via tf32 tensor cores.
// out[b][m][n] = sum_c W[m][c] * f(src[b][c][n]) + bias[m] (+ residual)
// f = optional per-(b,c) affine (fused GroupNorm).
// Block tile 64m x 64n, k-chunk 32. 8 warps: warp = (m-block 16, n-half 32).
// grid: (N/64, M/64, B), block 256.
// ---------------------------------------------------------------------------
__global__ void __launch_bounds__(256)
gemm_tf32(const float* __restrict__ W,
          const float* __restrict__ bias,
          const float* __restrict__ src,
          const float* __restrict__ resid,
          float* __restrict__ out, int M,
          const float* __restrict__ gA,
          const float* __restrict__ gB) {
    __shared__ float As[64][36];   // [m][c]  (A row-major frags)
    __shared__ float Bs[64][36];   // [n][c]  (B col-major frags)

    int b  = blockIdx.z;
    const float* Bp = src + (size_t)b * CCH * NSP;
    int m0 = blockIdx.y * 64, n0 = blockIdx.x * 64;

    int tid = threadIdx.x;
    int lane = tid & 31, w = tid >> 5;
    int g = lane >> 2, tig = lane & 3;
    int wm = (w & 3) * 16;       // warp m offset
    int wn = (w >> 2) * 32;      // warp n offset

    float4 Cf[4] = {{0,0,0,0},{0,0,0,0},{0,0,0,0},{0,0,0,0}};

    for (int k0 = 0; k0 < CCH; k0 += 32) {
        __syncthreads();
        // A: W[m0+m][k0 + c4..c4+3]   (512 float4)
        #pragma unroll
        for (int r = 0; r < 2; r++) {
            int i = tid + r * 256;
            int m = i >> 3, c4 = (i & 7) * 4;
            float4 wv = *(const float4*)&W[(size_t)(m0 + m) * CCH + k0 + c4];
            As[m][c4 + 0] = tf32r(wv.x);
            As[m][c4 + 1] = tf32r(wv.y);
            As[m][c4 + 2] = tf32r(wv.z);
            As[m][c4 + 3] = tf32r(wv.w);
        }
        // B: src[k0+c][n0 + n4..n4+3] transposed into Bs[n][c], GN affine fused
        #pragma unroll
        for (int r = 0; r < 2; r++) {
            int i = tid + r * 256;
            int c = i & 31, n4 = (i >> 5) * 4;
            float4 sv = *(const float4*)&Bp[(size_t)(k0 + c) * NSP + n0 + n4];
            float a = 1.f, s = 0.f;
            if (gA) { a = gA[b * CCH + k0 + c]; s = gB[b * CCH + k0 + c]; }
            Bs[n4 + 0][c] = tf32r(sv.x * a + s);
            Bs[n4 + 1][c] = tf32r(sv.y * a + s);
            Bs[n4 + 2][c] = tf32r(sv.z * a + s);
            Bs[n4 + 3][c] = tf32r(sv.w * a + s);
        }
        __syncthreads();

        #pragma unroll
        for (int kk = 0; kk < 32; kk += 8) {
            unsigned a0 = fu(As[wm + g][kk + tig]);
            unsigned a1 = fu(As[wm + g + 8][kk + tig]);
            unsigned a2 = fu(As[wm + g][kk + tig + 4]);
            unsigned a3 = fu(As[wm + g + 8][kk + tig + 4]);
            #pragma unroll
            for (int s = 0; s < 4; s++) {
                unsigned b0 = fu(Bs[wn + s * 8 + g][kk + tig]);
                unsigned b1 = fu(Bs[wn + s * 8 + g][kk + tig + 4]);
                mma_tf32(Cf[s], a0, a1, a2, a3, b0, b1);
            }
        }
    }

    // epilogue: C rows (g, g+8), cols 2tig, 2tig+1 per n-subtile
    #pragma unroll
    for (int s = 0; s < 4; s++) {
        int n  = n0 + wn + s * 8 + 2 * tig;
        int mA = m0 + wm + g;
        int mB = mA + 8;
        float bA = bias[mA], bB = bias[mB];
        size_t iA = (size_t)b * M * NSP + (size_t)mA * NSP + n;
        size_t iB = (size_t)b * M * NSP + (size_t)mB * NSP + n;
        float2 oA = make_float2(Cf[s].x + bA, Cf[s].y + bA);
        float2 oB = make_float2(Cf[s].z + bB, Cf[s].w + bB);
        if (resid) {
            float2 rA = *(const float2*)&resid[iA];
            float2 rB = *(const float2*)&resid[iB];
            oA.x += rA.x; oA.y += rA.y;
            oB.x += rB.x; oB.y += rB.y;
        }
        *(float2*)&out[iA] = oA;
        *(float2*)&out[iB] = oB;
    }
}

// ---------------------------------------------------------------------------
// Kernel 3: attention via tf32 tensor cores. Block = (b, head, 64-q tile).
// KT=64 key tile, 16 iterations. 8 warps:
//   S phase:  warp = (q-block w&3, k-half w>>2): 4 n-subtiles, k-chain d=32.
//   PV phase: warp = (q-block w&3, d-half w>>2): 2 n-subtiles, k-chain 64.
// Online softmax in base 2 (log2e folded into Q pre-scale), cross-warp
// combine through half-max/half-sum smem arrays. O stays in C-fragments.
// ---------------------------------------------------------------------------
__global__ void __launch_bounds__(256) attn_tf32() {
    __shared__ float Qs[64][36];   // [q][d]   tf32, pre-scaled
    __shared__ float Ks[64][36];   // [key][d] tf32
    __shared__ float Vs[32][68];   // [d][key] tf32
    __shared__ float Ss[64][68];   // P [q][key] tf32; reused as O staging [q][d]
    __shared__ float hm[2][64], hs[2][64];

    int blk = blockIdx.x;
    int qt  = blk & 15;
    int bh  = blk >> 4;            // b*8 + h
    const float* qb = g_qkv + (size_t)(bh >> 3) * 3 * CCH * NSP
                            + (size_t)((bh & 7) * HD) * NSP;
    const float* kb = qb + (size_t)CCH * NSP;
    const float* vb = kb + (size_t)CCH * NSP;
    int n0 = qt * 64;

    int tid = threadIdx.x;
    int lane = tid & 31, w = tid >> 5;
    int g = lane >> 2, tig = lane & 3;
    int qbk = (w & 3) * 16;        // q-block offset (S and PV)
    int kh  = w >> 2;              // k-half (S) / d-half (PV)
    const float qscale = 0.17677669529663687f * 1.4426950408889634f; // /sqrt(32)*log2e

    // Q load: gmem [d][q] -> Qs[q][d], scaled + tf32
    #pragma unroll
    for (int r = 0; r < 2; r++) {
        int i = tid + r * 256;
        int d = i >> 4, q4 = (i & 15) * 4;
        float4 v = *(const float4*)&qb[(size_t)d * NSP + n0 + q4];
        Qs[q4 + 0][d] = tf32r(v.x * qscale);
        Qs[q4 + 1][d] = tf32r(v.y * qscale);
        Qs[q4 + 2][d] = tf32r(v.z * qscale);
        Qs[q4 + 3][d] = tf32r(v.w * qscale);
    }

    float m_i[2] = {-1e30f, -1e30f};
    float l_i[2] = {0.f, 0.f};
    float4 Of[2] = {{0,0,0,0},{0,0,0,0}};
    int r0 = qbk + g, r1 = qbk + g + 8;

    for (int kt = 0; kt < 16; kt++) {
        __syncthreads();           // K/V/Ss readers of prev iter done
        int k0 = kt * 64;
        // K: gmem [d][key] -> Ks[key][d] (transposed, tf32)
        #pragma unroll
        for (int r = 0; r < 2; r++) {
            int i = tid + r * 256;
            int d = i >> 4, k4 = (i & 15) * 4;
            float4 v = *(const float4*)&kb[(size_t)d * NSP + k0 + k4];
            Ks[k4 + 0][d] = tf32r(v.x);
            Ks[k4 + 1][d] = tf32r(v.y);
            Ks[k4 + 2][d] = tf32r(v.z);
            Ks[k4 + 3][d] = tf32r(v.w);
        }
        // V: gmem [d][key] -> Vs[d][key] (direct, tf32)
        #pragma unroll
        for (int r = 0; r < 2; r++) {
            int i = tid + r * 256;
            int d = i >> 4, k4 = (i & 15) * 4;
            float4 v = *(const float4*)&vb[(size_t)d * NSP + k0 + k4];
            float4 t;
            t.x = tf32r(v.x); t.y = tf32r(v.y);
            t.z = tf32r(v.z); t.w = tf32r(v.w);
            *(float4*)&Vs[d][k4] = t;
        }
        __syncthreads();

        // ---- S = Q K^T on this warp's 16q x 32k quadrant ----
        float4 Sf[4] = {{0,0,0,0},{0,0,0,0},{0,0,0,0},{0,0,0,0}};
        #pragma unroll
        for (int kk = 0; kk < 32; kk += 8) {
            unsigned a0 = fu(Qs[r0][kk + tig]);
            unsigned a1 = fu(Qs[r1][kk + tig]);
            unsigned a2 = fu(Qs[r0][kk + tig + 4]);
            unsigned a3 = fu(Qs[r1][kk + tig + 4]);
            #pragma unroll
            for (int s = 0; s < 4; s++) {
                int kbse = kh * 32 + s * 8;
                unsigned b0 = fu(Ks[kbse + g][kk + tig]);
                unsigned b1 = fu(Ks[kbse + g][kk + tig + 4]);
                mma_tf32(Sf[s], a0, a1, a2, a3, b0, b1);
            }
        }

        // ---- half-row max (32 keys), combine across tig lanes ----
        float mx0 = fmaxf(fmaxf(Sf[0].x, Sf[0].y), fmaxf(Sf[1].x, Sf[1].y));
        mx0 = fmaxf(mx0, fmaxf(fmaxf(Sf[2].x, Sf[2].y), fmaxf(Sf[3].x, Sf[3].y)));
        float mx1 = fmaxf(fmaxf(Sf[0].z, Sf[0].w), fmaxf(Sf[1].z, Sf[1].w));
        mx1 = fmaxf(mx1, fmaxf(fmaxf(Sf[2].z, Sf[2].w), fmaxf(Sf[3].z, Sf[3].w)));
        mx0 = fmaxf(mx0, __shfl_xor_sync(0xffffffffu, mx0, 1));
        mx0 = fmaxf(mx0, __shfl_xor_sync(0xffffffffu, mx0, 2));
        mx1 = fmaxf(mx1, __shfl_xor_sync(0xffffffffu, mx1, 1));
        mx1 = fmaxf(mx1, __shfl_xor_sync(0xffffffffu, mx1, 2));
        if (tig == 0) { hm[kh][r0] = mx0; hm[kh][r1] = mx1; }
        __syncthreads();

        // ---- softmax update (base 2), write P (tf32) ----
        float mn0 = fmaxf(m_i[0], fmaxf(hm[0][r0], hm[1][r0]));
        float mn1 = fmaxf(m_i[1], fmaxf(hm[0][r1], hm[1][r1]));
        float c0 = ex2(m_i[0] - mn0), c1 = ex2(m_i[1] - mn1);
        m_i[0] = mn0; m_i[1] = mn1;
        float ls0 = 0.f, ls1 = 0.f;
        #pragma unroll
        for (int s = 0; s < 4; s++) {
            float p00 = ex2(Sf[s].x - mn0), p01 = ex2(Sf[s].y - mn0);
            float p10 = ex2(Sf[s].z - mn1), p11 = ex2(Sf[s].w - mn1);
            ls0 += p00 + p01; ls1 += p10 + p11;
            int col = kh * 32 + s * 8 + 2 * tig;
            Ss[r0][col] = tf32r(p00); Ss[r0][col + 1] = tf32r(p01);
            Ss[r1][col] = tf32r(p10); Ss[r1][col + 1] = tf32r(p11);
        }
        ls0 += __shfl_xor_sync(0xffffffffu, ls0, 1);
        ls0 += __shfl_xor_sync(0xffffffffu, ls0, 2);
        ls1 += __shfl_xor_sync(0xffffffffu, ls1, 1);
        ls1 += __shfl_xor_sync(0xffffffffu, ls1, 2);
        if (tig == 0) { hs[kh][r0] = ls0; hs[kh][r1] = ls1; }
        __syncthreads();

        l_i[0] = l_i[0] * c0 + hs[0][r0] + hs[1][r0];
        l_i[1] = l_i[1] * c1 + hs[0][r1] + hs[1][r1];

        // ---- rescale O, then O += P V^T (warp's 16q x 16d, k-chain 64) ----
        Of[0].x *= c0; Of[0].y *= c0; Of[0].z *= c1; Of[0].w *= c1;
        Of[1].x *= c0; Of[1].y *= c0; Of[1].z *= c1; Of[1].w *= c1;
        #pragma unroll
        for (int kk = 0; kk < 64; kk += 8) {
            unsigned a0 = fu(Ss[r0][kk + tig]);
            unsigned a1 = fu(Ss[r1][kk + tig]);
            unsigned a2 = fu(Ss[r0][kk + tig + 4]);
            unsigned a3 = fu(Ss[r1][kk + tig + 4]);
            #pragma unroll
            for (int s = 0; s < 2; s++) {
                int d0 = kh * 16 + s * 8;
                unsigned b0 = fu(Vs[d0 + g][kk + tig]);
                unsigned b1 = fu(Vs[d0 + g][kk + tig + 4]);
                mma_tf32(Of[s], a0, a1, a2, a3, b0, b1);
            }
        }
    }

    // ---- epilogue: normalize, stage O^T via smem, coalesced store ----
    __syncthreads();
    float i0 = 1.f / l_i[0], i1 = 1.f / l_i[1];
    #pragma unroll
    for (int s = 0; s < 2; s++) {
        int d0 = kh * 16 + s * 8 + 2 * tig;
        Ss[r0][d0]     = Of[s].x * i0;
        Ss[r0][d0 + 1] = Of[s].y * i0;
        Ss[r1][d0]     = Of[s].z * i1;
        Ss[r1][d0 + 1] = Of[s].w * i1;
    }
    __syncthreads();

    float* op = g_att + (size_t)bh * HD * NSP;
    for (int i = tid; i < 2048; i += 256) {
        int d = i >> 6, q = i & 63;
        op[(size_t)d * NSP + n0 + q] = Ss[q][d];
    }
}

// ---------------------------------------------------------------------------
extern "C" void kernel_launch(void* const* d_in, const int* in_sizes, int n_in,
                              void* d_out, int out_size) {
    const float* x        = (const float*)d_in[0];
    const float* gn_scale = (const float*)d_in[1];
    const float* gn_bias  = (const float*)d_in[2];
    const float* w_qkv    = (const float*)d_in[3];
    const float* b_qkv    = (const float*)d_in[4];
    const float* w_out    = (const float*)d_in[5];
    const float* b_out    = (const float*)d_in[6];
    float* out = (float*)d_out;

    float *pqkv, *patt, *psA, *psB;
    cudaGetSymbolAddress((void**)&pqkv, g_qkv);
    cudaGetSymbolAddress((void**)&patt, g_att);
    cudaGetSymbolAddress((void**)&psA,  g_sA);
    cudaGetSymbolAddress((void**)&psB,  g_sB);

    // 1. GroupNorm statistics (affine folded into QKV GEMM loads)
    gn_stats_kernel<<<BATCH * 8, 256>>>(x, gn_scale, gn_bias);
    // 2. QKV projection with fused GroupNorm: [768,256] @ [256,1024] per batch
    gemm_tf32<<<dim3(16, 12, BATCH), 256>>>(w_qkv, b_qkv, x, nullptr, pqkv,
                                            768, psA, psB);
    // 3. Attention
    attn_tf32<<<BATCH * HEADS * 16, 256>>>();
    // 4. Output projection + residual
    gemm_tf32<<<dim3(16, 4, BATCH), 256>>>(w_out, b_out, patt, x, out,
                                           256, nullptr, nullptr);
}

// round 5
// speedup vs baseline: 6.1508x; 2.2161x over previous
#include <cuda_runtime.h>
#include <cuda_fp16.h>

// Problem constants: B=8, C=256, H=W=32 -> N=1024, heads=8, hd=32, groups=8.
#define BATCH   8
#define CCH     256
#define NSP     1024
#define HEADS   8
#define HD      32

// ---- mma / ldmatrix helpers ------------------------------------------------
__device__ __forceinline__ unsigned smaddr(const void* p) {
    return (unsigned)__cvta_generic_to_shared(p);
}
__device__ __forceinline__ void ldsm4(unsigned& r0, unsigned& r1,
                                      unsigned& r2, unsigned& r3, unsigned a) {
    asm volatile("ldmatrix.sync.aligned.m8n8.x4.shared.b16 {%0,%1,%2,%3}, [%4];"
                 : "=r"(r0), "=r"(r1), "=r"(r2), "=r"(r3) : "r"(a));
}
__device__ __forceinline__ void ldsm4t(unsigned& r0, unsigned& r1,
                                       unsigned& r2, unsigned& r3, unsigned a) {
    asm volatile("ldmatrix.sync.aligned.m8n8.x4.trans.shared.b16 {%0,%1,%2,%3}, [%4];"
                 : "=r"(r0), "=r"(r1), "=r"(r2), "=r"(r3) : "r"(a));
}
__device__ __forceinline__ void mma16816(float4& d, unsigned a0, unsigned a1,
                                         unsigned a2, unsigned a3,
                                         unsigned b0, unsigned b1) {
    asm volatile("mma.sync.aligned.m16n8k16.row.col.f32.f16.f16.f32 "
        "{%0,%1,%2,%3},{%4,%5,%6,%7},{%8,%9},{%0,%1,%2,%3};"
        : "+f"(d.x), "+f"(d.y), "+f"(d.z), "+f"(d.w)
        : "r"(a0), "r"(a1), "r"(a2), "r"(a3), "r"(b0), "r"(b1));
}
__device__ __forceinline__ float ex2(float x) {
    float y; asm("ex2.approx.ftz.f32 %0, %1;" : "=f"(y) : "f"(x)); return y;
}

// Scratch (device globals; no allocation APIs allowed)
__device__ __half g_q[BATCH * HEADS * NSP * HD];  // [bh][q][d]  pre-scaled
__device__ __half g_k[BATCH * HEADS * NSP * HD];  // [bh][k][d]
__device__ __half g_v[BATCH * HEADS * HD * NSP];  // [bh][d][k]
__device__ __half g_o[BATCH * NSP * CCH];         // [b][n][c]   attention out
__device__ float  g_sA[BATCH * CCH];              // GN affine scale per (b,c)
__device__ float  g_sB[BATCH * CCH];              // GN affine shift per (b,c)

// ---------------------------------------------------------------------------
// Kernel 1: GroupNorm statistics only. One block per (b, group).
// ---------------------------------------------------------------------------
__global__ void gn_stats_kernel(const float* __restrict__ x,
                                const float* __restrict__ sc,
                                const float* __restrict__ bi) {
    int bg = blockIdx.x;            // b*8 + g
    int g  = bg & 7;
    const float4* xp = (const float4*)(x + (size_t)bg * 32 * NSP);

    int t = threadIdx.x;
    float s = 0.f, s2 = 0.f;
    for (int i = t; i < 8192; i += 256) {
        float4 v = xp[i];
        s  += v.x + v.y + v.z + v.w;
        s2 += v.x * v.x + v.y * v.y + v.z * v.z + v.w * v.w;
    }
    __shared__ float r1[256], r2[256];
    r1[t] = s; r2[t] = s2;
    __syncthreads();
    for (int st = 128; st > 0; st >>= 1) {
        if (t < st) { r1[t] += r1[t + st]; r2[t] += r2[t + st]; }
        __syncthreads();
    }
    float mean = r1[0] * (1.f / 32768.f);
    float var  = r2[0] * (1.f / 32768.f) - mean * mean;
    float inv  = rsqrtf(var + 1e-5f);

    if (t < 32) {
        int c = g * 32 + t;
        float a = inv * sc[c];
        g_sA[(bg >> 3) * CCH + c] = a;
        g_sB[(bg >> 3) * CCH + c] = bi[c] - mean * a;
    }
}

// ---------------------------------------------------------------------------
// Kernel 2: QKV GEMM (fp16 HMMA). qkv[b][m][n] = sum_c W[m][c]*(x*a+b) + bias
// Writes half outputs in attention-ready layouts (Q pre-scaled, V direct).
// Block 64m x 64n, k-chunk 64. 8 warps = (4m x 2n). grid (16, 12, B).
// ---------------------------------------------------------------------------
__global__ void __launch_bounds__(256)
gemm_qkv(const float* __restrict__ W,
         const float* __restrict__ bias,
         const float* __restrict__ x) {
    __shared__ __half As[64][72];   // [m][k] row-major
    __shared__ __half Bs[64][72];   // [k][n] row-major (B-frags via trans ldsm)

    int b  = blockIdx.z;
    const float* Bp = x + (size_t)b * CCH * NSP;
    int m0 = blockIdx.y * 64, n0 = blockIdx.x * 64;

    int tid = threadIdx.x, lane = tid & 31, w = tid >> 5;
    int g = lane >> 2, t = lane & 3;
    int wm = (w & 3) * 16, wn = (w >> 2) * 32;

    float4 Cf[4] = {{0,0,0,0},{0,0,0,0},{0,0,0,0},{0,0,0,0}};

    for (int k0 = 0; k0 < CCH; k0 += 64) {
        __syncthreads();
        #pragma unroll
        for (int r = 0; r < 4; r++) {           // A: W -> half
            int i = tid + r * 256;
            int m = i >> 4, k4 = (i & 15) * 4;
            float4 v = *(const float4*)&W[(size_t)(m0 + m) * CCH + k0 + k4];
            __half2* dst = (__half2*)&As[m][k4];
            dst[0] = __floats2half2_rn(v.x, v.y);
            dst[1] = __floats2half2_rn(v.z, v.w);
        }
        #pragma unroll
        for (int r = 0; r < 4; r++) {           // B: GN-affine(x) -> half
            int i = tid + r * 256;
            int c = i >> 4, n4 = (i & 15) * 4;
            float a = g_sA[b * CCH + k0 + c], s = g_sB[b * CCH + k0 + c];
            float4 v = *(const float4*)&Bp[(size_t)(k0 + c) * NSP + n0 + n4];
            __half2* dst = (__half2*)&Bs[c][n4];
            dst[0] = __floats2half2_rn(v.x * a + s, v.y * a + s);
            dst[1] = __floats2half2_rn(v.z * a + s, v.w * a + s);
        }
        __syncthreads();

        unsigned abase = smaddr(&As[wm + (lane & 15)][(lane >> 4) * 8]);
        unsigned bbase = smaddr(&Bs[(lane & 15)][wn + (lane >> 4) * 8]);
        #pragma unroll
        for (int kk = 0; kk < 64; kk += 16) {
            unsigned a0, a1, a2, a3;
            ldsm4(a0, a1, a2, a3, abase + kk * 2);
            #pragma unroll
            for (int p = 0; p < 2; p++) {
                unsigned b0, b1, b2, b3;
                ldsm4t(b0, b1, b2, b3, bbase + kk * 144 + p * 32);
                mma16816(Cf[2 * p],     a0, a1, a2, a3, b0, b1);
                mma16816(Cf[2 * p + 1], a0, a1, a2, a3, b2, b3);
            }
        }
    }

    // epilogue: scatter into Q/K/V half layouts (section uniform per block)
    const float qs = 0.17677669529663687f * 1.4426950408889634f; // 1/sqrt(32)*log2e
    int sect = m0 >> 8;                    // 0=Q, 1=K, 2=V
    #pragma unroll
    for (int s = 0; s < 4; s++) {
        int n = n0 + wn + s * 8 + 2 * t;
        #pragma unroll
        for (int rr = 0; rr < 2; rr++) {
            int m = m0 + wm + g + rr * 8;
            float bb = bias[m];
            float v0 = (rr ? Cf[s].z : Cf[s].x) + bb;
            float v1 = (rr ? Cf[s].w : Cf[s].y) + bb;
            int c  = m & 255;
            int bh = b * 8 + (c >> 5);
            int dd = c & 31;
            if (sect == 0) {
                g_q[((size_t)bh * NSP + n)     * HD + dd] = __float2half_rn(v0 * qs);
                g_q[((size_t)bh * NSP + n + 1) * HD + dd] = __float2half_rn(v1 * qs);
            } else if (sect == 1) {
                g_k[((size_t)bh * NSP + n)     * HD + dd] = __float2half_rn(v0);
                g_k[((size_t)bh * NSP + n + 1) * HD + dd] = __float2half_rn(v1);
            } else {
                *(__half2*)&g_v[((size_t)bh * HD + dd) * NSP + n] =
                    __floats2half2_rn(v0, v1);
            }
        }
    }
}

// ---------------------------------------------------------------------------
// Kernel 3: attention (fp16 HMMA + ldmatrix). Block = (b, head, 64-q tile).
// KT=128 key tile, 8 iterations, 4 barriers/iter. 8 warps:
//   S phase:  warp = (q-block w&3, 64-key half w>>2)
//   PV phase: warp = (q-block w&3, 16-dim half w>>2)
// Online softmax base-2 (log2e in Q pre-scale). Output -> g_o [b][n][c] half.
// ---------------------------------------------------------------------------
__global__ void __launch_bounds__(256) attn_h() {
    __shared__ __half Qs[64][40];    // [q][d]
    __shared__ __half Ks[128][40];   // [key][d]
    __shared__ __half Vs[32][136];   // [d][key]
    __shared__ __half Ps[64][136];   // P [q][key] half
    __shared__ float  hm[2][64], hs[2][64];

    int blk = blockIdx.x, qt = blk & 15, bh = blk >> 4;
    const __half* qp = g_q + (size_t)bh * NSP * HD;
    const __half* kp = g_k + (size_t)bh * NSP * HD;
    const __half* vp = g_v + (size_t)bh * HD * NSP;
    int n0 = qt * 64;

    int tid = threadIdx.x, lane = tid & 31, w = tid >> 5;
    int g = lane >> 2, t = lane & 3;
    int qbk = (w & 3) * 16, kh = w >> 2;
    int r0 = qbk + g, r1 = r0 + 8;

    {   // Q tile: 64 rows x 32 halves (pure copy, already scaled)
        int row = tid >> 2, part = tid & 3;
        *(float4*)&Qs[row][part * 8] =
            *(const float4*)&qp[(size_t)(n0 + row) * HD + part * 8];
    }

    float m_i[2] = {-1e30f, -1e30f}, l_i[2] = {0.f, 0.f};
    float4 Of[2] = {{0,0,0,0},{0,0,0,0}};

    unsigned qaddr = smaddr(&Qs[qbk + (lane & 15)][(lane >> 4) * 8]);
    unsigned kaddr = smaddr(&Ks[kh * 64 + ((lane >> 4) & 1) * 8 + (lane & 7)]
                               [((lane >> 3) & 1) * 8]);
    unsigned paddr = smaddr(&Ps[qbk + (lane & 15)][(lane >> 4) * 8]);
    unsigned vaddr = smaddr(&Vs[kh * 16 + ((lane >> 4) & 1) * 8 + (lane & 7)]
                               [((lane >> 3) & 1) * 8]);

    for (int kt = 0; kt < 8; kt++) {
        __syncthreads();
        int k0 = kt * 128;
        #pragma unroll
        for (int r = 0; r < 2; r++) {        // K: 128x32 half (copy)
            int i = tid + r * 256;
            int row = i >> 2, part = i & 3;
            *(float4*)&Ks[row][part * 8] =
                *(const float4*)&kp[(size_t)(k0 + row) * HD + part * 8];
        }
        #pragma unroll
        for (int r = 0; r < 2; r++) {        // V: 32x128 half (copy)
            int i = tid + r * 256;
            int dr = i >> 4, part = i & 15;
            *(float4*)&Vs[dr][part * 8] =
                *(const float4*)&vp[(size_t)dr * NSP + k0 + part * 8];
        }
        __syncthreads();

        // ---- S = Q K^T on this warp's 16q x 64k ----
        float4 Sf[8] = {{0,0,0,0},{0,0,0,0},{0,0,0,0},{0,0,0,0},
                        {0,0,0,0},{0,0,0,0},{0,0,0,0},{0,0,0,0}};
        #pragma unroll
        for (int ks = 0; ks < 2; ks++) {
            unsigned a0, a1, a2, a3;
            ldsm4(a0, a1, a2, a3, qaddr + ks * 32);
            #pragma unroll
            for (int p = 0; p < 4; p++) {
                unsigned b0, b1, b2, b3;
                ldsm4(b0, b1, b2, b3, kaddr + p * 1280 + ks * 32);
                mma16816(Sf[2 * p],     a0, a1, a2, a3, b0, b1);
                mma16816(Sf[2 * p + 1], a0, a1, a2, a3, b2, b3);
            }
        }

        // ---- half-row max over 64 keys ----
        float mx0 = -1e30f, mx1 = -1e30f;
        #pragma unroll
        for (int s = 0; s < 8; s++) {
            mx0 = fmaxf(mx0, fmaxf(Sf[s].x, Sf[s].y));
            mx1 = fmaxf(mx1, fmaxf(Sf[s].z, Sf[s].w));
        }
        mx0 = fmaxf(mx0, __shfl_xor_sync(0xffffffffu, mx0, 1));
        mx0 = fmaxf(mx0, __shfl_xor_sync(0xffffffffu, mx0, 2));
        mx1 = fmaxf(mx1, __shfl_xor_sync(0xffffffffu, mx1, 1));
        mx1 = fmaxf(mx1, __shfl_xor_sync(0xffffffffu, mx1, 2));
        if (t == 0) { hm[kh][r0] = mx0; hm[kh][r1] = mx1; }
        __syncthreads();

        // ---- softmax update (base 2), write P as half ----
        float mn0 = fmaxf(m_i[0], fmaxf(hm[0][r0], hm[1][r0]));
        float mn1 = fmaxf(m_i[1], fmaxf(hm[0][r1], hm[1][r1]));
        float c0 = ex2(m_i[0] - mn0), c1 = ex2(m_i[1] - mn1);
        m_i[0] = mn0; m_i[1] = mn1;
        float ls0 = 0.f, ls1 = 0.f;
        #pragma unroll
        for (int s = 0; s < 8; s++) {
            float p00 = ex2(Sf[s].x - mn0), p01 = ex2(Sf[s].y - mn0);
            float p10 = ex2(Sf[s].z - mn1), p11 = ex2(Sf[s].w - mn1);
            ls0 += p00 + p01; ls1 += p10 + p11;
            int col = kh * 64 + s * 8 + 2 * t;
            *(__half2*)&Ps[r0][col] = __floats2half2_rn(p00, p01);
            *(__half2*)&Ps[r1][col] = __floats2half2_rn(p10, p11);
        }
        ls0 += __shfl_xor_sync(0xffffffffu, ls0, 1);
        ls0 += __shfl_xor_sync(0xffffffffu, ls0, 2);
        ls1 += __shfl_xor_sync(0xffffffffu, ls1, 1);
        ls1 += __shfl_xor_sync(0xffffffffu, ls1, 2);
        if (t == 0) { hs[kh][r0] = ls0; hs[kh][r1] = ls1; }
        __syncthreads();

        l_i[0] = l_i[0] * c0 + hs[0][r0] + hs[1][r0];
        l_i[1] = l_i[1] * c1 + hs[0][r1] + hs[1][r1];

        // ---- O = O*corr + P V^T : warp's 16q x 16d, k-chain 128 ----
        Of[0].x *= c0; Of[0].y *= c0; Of[0].z *= c1; Of[0].w *= c1;
        Of[1].x *= c0; Of[1].y *= c0; Of[1].z *= c1; Of[1].w *= c1;
        #pragma unroll
        for (int kk = 0; kk < 8; kk++) {
            unsigned a0, a1, a2, a3, b0, b1, b2, b3;
            ldsm4(a0, a1, a2, a3, paddr + kk * 32);
            ldsm4(b0, b1, b2, b3, vaddr + kk * 32);
            mma16816(Of[0], a0, a1, a2, a3, b0, b1);
            mma16816(Of[1], a0, a1, a2, a3, b2, b3);
        }
    }

    // ---- epilogue: normalize, store half [b][n][c] (out-proj B layout) ----
    float i0 = 1.f / l_i[0], i1 = 1.f / l_i[1];
    int b_ = bh >> 3, h_ = bh & 7;
    #pragma unroll
    for (int s = 0; s < 2; s++) {
        int d = kh * 16 + s * 8 + 2 * t;
        size_t iA = ((size_t)b_ * NSP + n0 + r0) * CCH + h_ * 32 + d;
        size_t iB = ((size_t)b_ * NSP + n0 + r1) * CCH + h_ * 32 + d;
        *(__half2*)&g_o[iA] = __floats2half2_rn(Of[s].x * i0, Of[s].y * i0);
        *(__half2*)&g_o[iB] = __floats2half2_rn(Of[s].z * i1, Of[s].w * i1);
    }
}

// ---------------------------------------------------------------------------
// Kernel 4: out-projection GEMM (fp16 HMMA) + bias + fp32 residual.
// B operand = g_o [n][c] half (direct copy into smem, non-trans ldsm).
// ---------------------------------------------------------------------------
__global__ void __launch_bounds__(256)
gemm_out(const float* __restrict__ W,
         const float* __restrict__ bias,
         const float* __restrict__ resid,
         float* __restrict__ out) {
    __shared__ __half As[64][72];   // [m][k]
    __shared__ __half Bs[64][72];   // [n][k]

    int b  = blockIdx.z;
    const __half* src = g_o + (size_t)b * NSP * CCH;
    int m0 = blockIdx.y * 64, n0 = blockIdx.x * 64;

    int tid = threadIdx.x, lane = tid & 31, w = tid >> 5;
    int g = lane >> 2, t = lane & 3;
    int wm = (w & 3) * 16, wn = (w >> 2) * 32;

    float4 Cf[4] = {{0,0,0,0},{0,0,0,0},{0,0,0,0},{0,0,0,0}};

    for (int k0 = 0; k0 < CCH; k0 += 64) {
        __syncthreads();
        #pragma unroll
        for (int r = 0; r < 4; r++) {           // A: w_out -> half
            int i = tid + r * 256;
            int m = i >> 4, k4 = (i & 15) * 4;
            float4 v = *(const float4*)&W[(size_t)(m0 + m) * CCH + k0 + k4];
            __half2* dst = (__half2*)&As[m][k4];
            dst[0] = __floats2half2_rn(v.x, v.y);
            dst[1] = __floats2half2_rn(v.z, v.w);
        }
        #pragma unroll
        for (int r = 0; r < 2; r++) {           // B: pure half copy [n][c]
            int i = tid + r * 256;
            int n = i >> 3, c8 = (i & 7) * 8;
            *(float4*)&Bs[n][c8] =
                *(const float4*)&src[(size_t)(n0 + n) * CCH + k0 + c8];
        }
        __syncthreads();

        unsigned abase = smaddr(&As[wm + (lane & 15)][(lane >> 4) * 8]);
        unsigned bbase = smaddr(&Bs[wn + ((lane >> 4) & 1) * 8 + (lane & 7)]
                                   [((lane >> 3) & 1) * 8]);
        #pragma unroll
        for (int kk = 0; kk < 64; kk += 16) {
            unsigned a0, a1, a2, a3;
            ldsm4(a0, a1, a2, a3, abase + kk * 2);
            #pragma unroll
            for (int p = 0; p < 2; p++) {
                unsigned b0, b1, b2, b3;
                ldsm4(b0, b1, b2, b3, bbase + p * 2304 + kk * 2);
                mma16816(Cf[2 * p],     a0, a1, a2, a3, b0, b1);
                mma16816(Cf[2 * p + 1], a0, a1, a2, a3, b2, b3);
            }
        }
    }

    #pragma unroll
    for (int s = 0; s < 4; s++) {
        int n  = n0 + wn + s * 8 + 2 * t;
        int mA = m0 + wm + g, mB = mA + 8;
        float bA = bias[mA], bB = bias[mB];
        size_t iA = ((size_t)b * CCH + mA) * NSP + n;
        size_t iB = ((size_t)b * CCH + mB) * NSP + n;
        float2 rA = *(const float2*)&resid[iA];
        float2 rB = *(const float2*)&resid[iB];
        *(float2*)&out[iA] = make_float2(Cf[s].x + bA + rA.x, Cf[s].y + bA + rA.y);
        *(float2*)&out[iB] = make_float2(Cf[s].z + bB + rB.x, Cf[s].w + bB + rB.y);
    }
}

// ---------------------------------------------------------------------------
extern "C" void kernel_launch(void* const* d_in, const int* in_sizes, int n_in,
                              void* d_out, int out_size) {
    const float* x        = (const float*)d_in[0];
    const float* gn_scale = (const float*)d_in[1];
    const float* gn_bias  = (const float*)d_in[2];
    const float* w_qkv    = (const float*)d_in[3];
    const float* b_qkv    = (const float*)d_in[4];
    const float* w_out    = (const float*)d_in[5];
    const float* b_out    = (const float*)d_in[6];
    float* out = (float*)d_out;

    // 1. GroupNorm statistics (affine folded into QKV GEMM loads)
    gn_stats_kernel<<<BATCH * 8, 256>>>(x, gn_scale, gn_bias);
    // 2. QKV projection (fused GN) -> half Q/K/V in attention layouts
    gemm_qkv<<<dim3(16, 12, BATCH), 256>>>(w_qkv, b_qkv, x);
    // 3. Attention -> half [b][n][c]
    attn_h<<<BATCH * HEADS * 16, 256>>>();
    // 4. Output projection + bias + fp32 residual
    gemm_out<<<dim3(16, 4, BATCH), 256>>>(w_out, b_out, x, out);
}

// round 6
// speedup vs baseline: 7.9187x; 1.2874x over previous
#include <cuda_runtime.h>
#include <cuda_fp16.h>

// Problem constants: B=8, C=256, H=W=32 -> N=1024, heads=8, hd=32, groups=8.
#define BATCH   8
#define CCH     256
#define NSP     1024
#define HEADS   8
#define HD      32

// ---- mma / ldmatrix / cp.async helpers -------------------------------------
__device__ __forceinline__ unsigned smaddr(const void* p) {
    return (unsigned)__cvta_generic_to_shared(p);
}
__device__ __forceinline__ void ldsm4(unsigned& r0, unsigned& r1,
                                      unsigned& r2, unsigned& r3, unsigned a) {
    asm volatile("ldmatrix.sync.aligned.m8n8.x4.shared.b16 {%0,%1,%2,%3}, [%4];"
                 : "=r"(r0), "=r"(r1), "=r"(r2), "=r"(r3) : "r"(a));
}
__device__ __forceinline__ void ldsm4t(unsigned& r0, unsigned& r1,
                                       unsigned& r2, unsigned& r3, unsigned a) {
    asm volatile("ldmatrix.sync.aligned.m8n8.x4.trans.shared.b16 {%0,%1,%2,%3}, [%4];"
                 : "=r"(r0), "=r"(r1), "=r"(r2), "=r"(r3) : "r"(a));
}
__device__ __forceinline__ void mma16816(float4& d, unsigned a0, unsigned a1,
                                         unsigned a2, unsigned a3,
                                         unsigned b0, unsigned b1) {
    asm volatile("mma.sync.aligned.m16n8k16.row.col.f32.f16.f16.f32 "
        "{%0,%1,%2,%3},{%4,%5,%6,%7},{%8,%9},{%0,%1,%2,%3};"
        : "+f"(d.x), "+f"(d.y), "+f"(d.z), "+f"(d.w)
        : "r"(a0), "r"(a1), "r"(a2), "r"(a3), "r"(b0), "r"(b1));
}
__device__ __forceinline__ float ex2(float x) {
    float y; asm("ex2.approx.ftz.f32 %0, %1;" : "=f"(y) : "f"(x)); return y;
}
__device__ __forceinline__ void cp16(void* dst, const void* src) {
    asm volatile("cp.async.cg.shared.global [%0], [%1], 16;"
                 :: "r"(smaddr(dst)), "l"(src));
}
__device__ __forceinline__ void cp_commit() {
    asm volatile("cp.async.commit_group;");
}
template <int N> __device__ __forceinline__ void cp_wait() {
    asm volatile("cp.async.wait_group %0;" :: "n"(N));
}
__device__ __forceinline__ unsigned h2u(__half2 h) {
    return *(unsigned*)&h;
}

// Scratch (device globals; no allocation APIs allowed)
__device__ __half g_xh[BATCH * CCH * NSP];        // group-normed x, half [b][c][n]
__device__ __half g_wq[3 * CCH * CCH];            // w_qkv half [m][k]
__device__ __half g_wo[CCH * CCH];                // w_out half [m][k]
__device__ __half g_q[BATCH * HEADS * NSP * HD];  // [bh][q][d] pre-scaled
__device__ __half g_k[BATCH * HEADS * NSP * HD];  // [bh][k][d]
__device__ __half g_v[BATCH * HEADS * HD * NSP];  // [bh][d][k]
__device__ __half g_o[BATCH * NSP * CCH];         // [b][n][c] attention out

// ---------------------------------------------------------------------------
// Kernel 0: convert weights fp32 -> fp16 (one-shot per launch).
// ---------------------------------------------------------------------------
__global__ void conv_w(const float* __restrict__ wq, const float* __restrict__ wo) {
    int i = blockIdx.x * blockDim.x + threadIdx.x;   // one float4 each
    if (i < 49152) {                                  // 768*256/4
        float4 v = ((const float4*)wq)[i];
        __half2* d = (__half2*)&g_wq[i * 4];
        d[0] = __floats2half2_rn(v.x, v.y);
        d[1] = __floats2half2_rn(v.z, v.w);
    } else {
        int j = i - 49152;                            // 256*256/4
        float4 v = ((const float4*)wo)[j];
        __half2* d = (__half2*)&g_wo[j * 4];
        d[0] = __floats2half2_rn(v.x, v.y);
        d[1] = __floats2half2_rn(v.z, v.w);
    }
}

// ---------------------------------------------------------------------------
// Kernel 1: GroupNorm -> half. One block per (b, group).
// ---------------------------------------------------------------------------
__global__ void gn_kernel(const float* __restrict__ x,
                          const float* __restrict__ sc,
                          const float* __restrict__ bi) {
    int bg = blockIdx.x;            // b*8 + g
    int g  = bg & 7;
    const float4* xp = (const float4*)(x + (size_t)bg * 32 * NSP);
    __half2* hp = (__half2*)(g_xh + (size_t)bg * 32 * NSP);

    int t = threadIdx.x;
    float s = 0.f, s2 = 0.f;
    for (int i = t; i < 8192; i += 256) {
        float4 v = xp[i];
        s  += v.x + v.y + v.z + v.w;
        s2 += v.x * v.x + v.y * v.y + v.z * v.z + v.w * v.w;
    }
    __shared__ float r1[256], r2[256];
    r1[t] = s; r2[t] = s2;
    __syncthreads();
    for (int st = 128; st > 0; st >>= 1) {
        if (t < st) { r1[t] += r1[t + st]; r2[t] += r2[t + st]; }
        __syncthreads();
    }
    float mean = r1[0] * (1.f / 32768.f);
    float var  = r2[0] * (1.f / 32768.f) - mean * mean;
    float inv  = rsqrtf(var + 1e-5f);

    for (int i = t; i < 8192; i += 256) {
        int c = g * 32 + (i >> 8);
        float a = inv * sc[c];
        float b = bi[c] - mean * a;
        float4 v = xp[i];
        hp[i * 2]     = __floats2half2_rn(v.x * a + b, v.y * a + b);
        hp[i * 2 + 1] = __floats2half2_rn(v.z * a + b, v.w * a + b);
    }
}

// ---------------------------------------------------------------------------
// Kernel 2/4: fp16 GEMM, cp.async double-buffered. 64m x 64n tile, k-chunk 64.
// MODE 0: qkv.  B = g_xh [k][n] (trans ldsm). Epilogue scatters Q/K/V.
// MODE 1: out.  B = g_o  [n][k] (ldsm).       Epilogue bias + fp32 residual.
// 8 warps = (4m x 2n), warp tile 16m x 32n. grid (16, M/64, B).
// ---------------------------------------------------------------------------
template <int MODE>
__global__ void __launch_bounds__(256)
gemm_h(const __half* __restrict__ A,     // weights [M][256] half
       const float* __restrict__ bias,
       const float* __restrict__ resid,  // MODE 1 only
       float* __restrict__ out) {        // MODE 1 only
    __shared__ __half As[2][64][72];
    __shared__ __half Bs[2][64][72];

    int b  = blockIdx.z;
    int m0 = blockIdx.y * 64, n0 = blockIdx.x * 64;
    const __half* Bsrc = (MODE == 0)
        ? g_xh + (size_t)b * CCH * NSP
        : g_o  + (size_t)b * NSP * CCH;

    int tid = threadIdx.x, lane = tid & 31, w = tid >> 5;
    int g = lane >> 2, t = lane & 3;
    int wm = (w & 3) * 16, wn = (w >> 2) * 32;

    // per-thread load slots: 2 chunks of 16B for A, 2 for B
    int lm  = tid >> 3, lk8 = (tid & 7) * 8;      // A: row, col8
    int lm2 = lm + 32;

    auto load_tile = [&](int buf, int k0) {
        cp16(&As[buf][lm][lk8],  &A[(size_t)(m0 + lm) * CCH + k0 + lk8]);
        cp16(&As[buf][lm2][lk8], &A[(size_t)(m0 + lm2) * CCH + k0 + lk8]);
        if (MODE == 0) {   // B rows = k, cols = n
            cp16(&Bs[buf][lm][lk8],  &Bsrc[(size_t)(k0 + lm) * NSP + n0 + lk8]);
            cp16(&Bs[buf][lm2][lk8], &Bsrc[(size_t)(k0 + lm2) * NSP + n0 + lk8]);
        } else {           // B rows = n, cols = k
            cp16(&Bs[buf][lm][lk8],  &Bsrc[(size_t)(n0 + lm) * CCH + k0 + lk8]);
            cp16(&Bs[buf][lm2][lk8], &Bsrc[(size_t)(n0 + lm2) * CCH + k0 + lk8]);
        }
    };

    float4 Cf[4] = {{0,0,0,0},{0,0,0,0},{0,0,0,0},{0,0,0,0}};

    load_tile(0, 0);
    cp_commit();

    #pragma unroll
    for (int it = 0; it < 4; it++) {
        int buf = it & 1;
        if (it < 3) { load_tile(buf ^ 1, (it + 1) * 64); cp_commit(); }
        if (it < 3) cp_wait<1>(); else cp_wait<0>();
        __syncthreads();

        unsigned abase = smaddr(&As[buf][wm + (lane & 15)][((lane >> 4) & 1) * 8]);
        unsigned bbase;
        if (MODE == 0)
            bbase = smaddr(&Bs[buf][(lane & 15)][wn + ((lane >> 4) & 1) * 8]);
        else
            bbase = smaddr(&Bs[buf][wn + ((lane >> 4) & 1) * 8 + (lane & 7)]
                                   [((lane >> 3) & 1) * 8]);
        #pragma unroll
        for (int kk = 0; kk < 64; kk += 16) {
            unsigned a0, a1, a2, a3;
            ldsm4(a0, a1, a2, a3, abase + kk * 2);
            #pragma unroll
            for (int p = 0; p < 2; p++) {
                unsigned b0, b1, b2, b3;
                if (MODE == 0)
                    ldsm4t(b0, b1, b2, b3, bbase + kk * 144 + p * 32);
                else
                    ldsm4(b0, b1, b2, b3, bbase + p * 2304 + kk * 2);
                mma16816(Cf[2 * p],     a0, a1, a2, a3, b0, b1);
                mma16816(Cf[2 * p + 1], a0, a1, a2, a3, b2, b3);
            }
        }
        __syncthreads();
    }

    if (MODE == 0) {
        // scatter into Q/K/V half layouts (section uniform per block)
        const float qs = 0.17677669529663687f * 1.4426950408889634f;
        int sect = m0 >> 8;                    // 0=Q, 1=K, 2=V
        #pragma unroll
        for (int s = 0; s < 4; s++) {
            int n = n0 + wn + s * 8 + 2 * t;
            #pragma unroll
            for (int rr = 0; rr < 2; rr++) {
                int m = m0 + wm + g + rr * 8;
                float bb = bias[m];
                float v0 = (rr ? Cf[s].z : Cf[s].x) + bb;
                float v1 = (rr ? Cf[s].w : Cf[s].y) + bb;
                int c  = m & 255;
                int bh = b * 8 + (c >> 5);
                int dd = c & 31;
                if (sect == 0) {
                    g_q[((size_t)bh * NSP + n)     * HD + dd] = __float2half_rn(v0 * qs);
                    g_q[((size_t)bh * NSP + n + 1) * HD + dd] = __float2half_rn(v1 * qs);
                } else if (sect == 1) {
                    g_k[((size_t)bh * NSP + n)     * HD + dd] = __float2half_rn(v0);
                    g_k[((size_t)bh * NSP + n + 1) * HD + dd] = __float2half_rn(v1);
                } else {
                    *(__half2*)&g_v[((size_t)bh * HD + dd) * NSP + n] =
                        __floats2half2_rn(v0, v1);
                }
            }
        }
    } else {
        #pragma unroll
        for (int s = 0; s < 4; s++) {
            int n  = n0 + wn + s * 8 + 2 * t;
            int mA = m0 + wm + g, mB = mA + 8;
            float bA = bias[mA], bB = bias[mB];
            size_t iA = ((size_t)b * CCH + mA) * NSP + n;
            size_t iB = ((size_t)b * CCH + mB) * NSP + n;
            float2 rA = *(const float2*)&resid[iA];
            float2 rB = *(const float2*)&resid[iB];
            *(float2*)&out[iA] = make_float2(Cf[s].x + bA + rA.x, Cf[s].y + bA + rA.y);
            *(float2*)&out[iB] = make_float2(Cf[s].z + bB + rB.x, Cf[s].w + bB + rB.y);
        }
    }
}

// ---------------------------------------------------------------------------
// Kernel 3: attention. Block = (b, head, 128-q tile); 8 warps, each warp owns
// 16 full query rows -> softmax entirely warp-local, P stays in registers
// (C-frag -> A-frag identity). KT=128, 8 iterations, 2 barriers each.
// ---------------------------------------------------------------------------
__global__ void __launch_bounds__(256, 2) attn_h() {
    __shared__ __half Qs[128][40];   // [q][d] staging for Q fragment loads
    __shared__ __half Ks[128][40];   // [key][d]
    __shared__ __half Vs[32][136];   // [d][key]

    int blk = blockIdx.x, qt = blk & 7, bh = blk >> 3;
    const __half* qp = g_q + (size_t)bh * NSP * HD;
    const __half* kp = g_k + (size_t)bh * NSP * HD;
    const __half* vp = g_v + (size_t)bh * HD * NSP;
    int n0 = qt * 128;

    int tid = threadIdx.x, lane = tid & 31, w = tid >> 5;
    int g = lane >> 2, t = lane & 3;

    // ---- stage Q tile, pull fragments to registers, then Qs is dead ----
    #pragma unroll
    for (int r = 0; r < 2; r++) {
        int i = tid + r * 256;
        int row = i >> 2, part = (i & 3) * 8;
        *(float4*)&Qs[row][part] =
            *(const float4*)&qp[(size_t)(n0 + row) * HD + part];
    }
    __syncthreads();
    unsigned qa[8];
    {
        unsigned qaddr = smaddr(&Qs[w * 16 + (lane & 15)][((lane >> 4) & 1) * 8]);
        ldsm4(qa[0], qa[1], qa[2], qa[3], qaddr);        // d 0..15
        ldsm4(qa[4], qa[5], qa[6], qa[7], qaddr + 32);   // d 16..31
    }

    unsigned kaddr = smaddr(&Ks[((lane >> 4) & 1) * 8 + (lane & 7)]
                               [((lane >> 3) & 1) * 8]);
    unsigned vaddr = smaddr(&Vs[((lane >> 4) & 1) * 8 + (lane & 7)]
                               [((lane >> 3) & 1) * 8]);

    float m0r = -1e30f, m1r = -1e30f, l0 = 0.f, l1 = 0.f;
    float4 Of[4] = {{0,0,0,0},{0,0,0,0},{0,0,0,0},{0,0,0,0}};

    for (int kt = 0; kt < 8; kt++) {
        __syncthreads();
        int k0 = kt * 128;
        #pragma unroll
        for (int r = 0; r < 2; r++) {        // K: 128 x 32 half
            int i = tid + r * 256;
            int row = i >> 2, part = (i & 3) * 8;
            *(float4*)&Ks[row][part] =
                *(const float4*)&kp[(size_t)(k0 + row) * HD + part];
        }
        #pragma unroll
        for (int r = 0; r < 2; r++) {        // V: 32 x 128 half
            int i = tid + r * 256;
            int dr = i >> 4, part = (i & 15) * 8;
            *(float4*)&Vs[dr][part] =
                *(const float4*)&vp[(size_t)dr * NSP + k0 + part];
        }
        __syncthreads();

        // ---- S = Q K^T : warp's 16q x 128k in registers ----
        float4 Sf[16];
        #pragma unroll
        for (int s = 0; s < 16; s++) Sf[s] = make_float4(0.f, 0.f, 0.f, 0.f);
        #pragma unroll
        for (int p = 0; p < 8; p++) {        // 16 keys per p
            unsigned b0, b1, b2, b3;
            ldsm4(b0, b1, b2, b3, kaddr + p * 1280);        // d 0..15
            mma16816(Sf[2 * p],     qa[0], qa[1], qa[2], qa[3], b0, b1);
            mma16816(Sf[2 * p + 1], qa[0], qa[1], qa[2], qa[3], b2, b3);
            ldsm4(b0, b1, b2, b3, kaddr + p * 1280 + 32);   // d 16..31
            mma16816(Sf[2 * p],     qa[4], qa[5], qa[6], qa[7], b0, b1);
            mma16816(Sf[2 * p + 1], qa[4], qa[5], qa[6], qa[7], b2, b3);
        }

        // ---- warp-local online softmax (base 2) ----
        float mx0 = -1e30f, mx1 = -1e30f;
        #pragma unroll
        for (int s = 0; s < 16; s++) {
            mx0 = fmaxf(mx0, fmaxf(Sf[s].x, Sf[s].y));
            mx1 = fmaxf(mx1, fmaxf(Sf[s].z, Sf[s].w));
        }
        mx0 = fmaxf(mx0, __shfl_xor_sync(0xffffffffu, mx0, 1));
        mx0 = fmaxf(mx0, __shfl_xor_sync(0xffffffffu, mx0, 2));
        mx1 = fmaxf(mx1, __shfl_xor_sync(0xffffffffu, mx1, 1));
        mx1 = fmaxf(mx1, __shfl_xor_sync(0xffffffffu, mx1, 2));
        float mn0 = fmaxf(m0r, mx0), mn1 = fmaxf(m1r, mx1);
        float c0 = ex2(m0r - mn0), c1 = ex2(m1r - mn1);
        m0r = mn0; m1r = mn1;
        float ls0 = 0.f, ls1 = 0.f;
        #pragma unroll
        for (int s = 0; s < 16; s++) {
            Sf[s].x = ex2(Sf[s].x - mn0);
            Sf[s].y = ex2(Sf[s].y - mn0);
            Sf[s].z = ex2(Sf[s].z - mn1);
            Sf[s].w = ex2(Sf[s].w - mn1);
            ls0 += Sf[s].x + Sf[s].y;
            ls1 += Sf[s].z + Sf[s].w;
        }
        ls0 += __shfl_xor_sync(0xffffffffu, ls0, 1);
        ls0 += __shfl_xor_sync(0xffffffffu, ls0, 2);
        ls1 += __shfl_xor_sync(0xffffffffu, ls1, 1);
        ls1 += __shfl_xor_sync(0xffffffffu, ls1, 2);
        l0 = l0 * c0 + ls0;
        l1 = l1 * c1 + ls1;

        // ---- O = O*corr + P V^T, P built in registers from Sf ----
        #pragma unroll
        for (int s = 0; s < 4; s++) {
            Of[s].x *= c0; Of[s].y *= c0; Of[s].z *= c1; Of[s].w *= c1;
        }
        #pragma unroll
        for (int kk = 0; kk < 8; kk++) {     // 16 keys per chain
            unsigned pa0 = h2u(__floats2half2_rn(Sf[2*kk].x,   Sf[2*kk].y));
            unsigned pa1 = h2u(__floats2half2_rn(Sf[2*kk].z,   Sf[2*kk].w));
            unsigned pa2 = h2u(__floats2half2_rn(Sf[2*kk+1].x, Sf[2*kk+1].y));
            unsigned pa3 = h2u(__floats2half2_rn(Sf[2*kk+1].z, Sf[2*kk+1].w));
            unsigned b0, b1, b2, b3;
            ldsm4(b0, b1, b2, b3, vaddr + kk * 32);          // d 0..15
            mma16816(Of[0], pa0, pa1, pa2, pa3, b0, b1);
            mma16816(Of[1], pa0, pa1, pa2, pa3, b2, b3);
            ldsm4(b0, b1, b2, b3, vaddr + 4352 + kk * 32);   // d 16..31
            mma16816(Of[2], pa0, pa1, pa2, pa3, b0, b1);
            mma16816(Of[3], pa0, pa1, pa2, pa3, b2, b3);
        }
    }

    // ---- epilogue: normalize, store half [b][n][c] ----
    float i0 = 1.f / l0, i1 = 1.f / l1;
    int b_ = bh >> 3, h_ = bh & 7;
    int nr0 = n0 + w * 16 + g, nr1 = nr0 + 8;
    #pragma unroll
    for (int s = 0; s < 4; s++) {
        int d = s * 8 + 2 * t;
        size_t iA = ((size_t)b_ * NSP + nr0) * CCH + h_ * 32 + d;
        size_t iB = ((size_t)b_ * NSP + nr1) * CCH + h_ * 32 + d;
        *(__half2*)&g_o[iA] = __floats2half2_rn(Of[s].x * i0, Of[s].y * i0);
        *(__half2*)&g_o[iB] = __floats2half2_rn(Of[s].z * i1, Of[s].w * i1);
    }
}

// ---------------------------------------------------------------------------
extern "C" void kernel_launch(void* const* d_in, const int* in_sizes, int n_in,
                              void* d_out, int out_size) {
    const float* x        = (const float*)d_in[0];
    const float* gn_scale = (const float*)d_in[1];
    const float* gn_bias  = (const float*)d_in[2];
    const float* w_qkv    = (const float*)d_in[3];
    const float* b_qkv    = (const float*)d_in[4];
    const float* w_out    = (const float*)d_in[5];
    const float* b_out    = (const float*)d_in[6];
    float* out = (float*)d_out;

    const __half *pwq, *pwo;
    cudaGetSymbolAddress((void**)&pwq, g_wq);
    cudaGetSymbolAddress((void**)&pwo, g_wo);

    // 0. Weight conversion fp32->fp16
    conv_w<<<256, 256>>>(w_qkv, w_out);
    // 1. GroupNorm -> half
    gn_kernel<<<BATCH * 8, 256>>>(x, gn_scale, gn_bias);
    // 2. QKV projection -> half Q/K/V in attention layouts
    gemm_h<0><<<dim3(16, 12, BATCH), 256>>>(pwq, b_qkv, nullptr, nullptr);
    // 3. Attention -> half [b][n][c]
    attn_h<<<BATCH * HEADS * 8, 256>>>();
    // 4. Output projection + bias + fp32 residual
    gemm_h<1><<<dim3(16, 4, BATCH), 256>>>(pwo, b_out, x, out);
}

// round 7
// speedup vs baseline: 8.2696x; 1.0443x over previous
#include <cuda_runtime.h>
#include <cuda_fp16.h>

// Problem constants: B=8, C=256, H=W=32 -> N=1024, heads=8, hd=32, groups=8.
#define BATCH   8
#define CCH     256
#define NSP     1024
#define HEADS   8
#define HD      32

// ---- mma / ldmatrix / cp.async helpers -------------------------------------
__device__ __forceinline__ unsigned smaddr(const void* p) {
    return (unsigned)__cvta_generic_to_shared(p);
}
__device__ __forceinline__ void ldsm4(unsigned& r0, unsigned& r1,
                                      unsigned& r2, unsigned& r3, unsigned a) {
    asm volatile("ldmatrix.sync.aligned.m8n8.x4.shared.b16 {%0,%1,%2,%3}, [%4];"
                 : "=r"(r0), "=r"(r1), "=r"(r2), "=r"(r3) : "r"(a));
}
__device__ __forceinline__ void ldsm4t(unsigned& r0, unsigned& r1,
                                       unsigned& r2, unsigned& r3, unsigned a) {
    asm volatile("ldmatrix.sync.aligned.m8n8.x4.trans.shared.b16 {%0,%1,%2,%3}, [%4];"
                 : "=r"(r0), "=r"(r1), "=r"(r2), "=r"(r3) : "r"(a));
}
__device__ __forceinline__ void mma16816(float4& d, unsigned a0, unsigned a1,
                                         unsigned a2, unsigned a3,
                                         unsigned b0, unsigned b1) {
    asm volatile("mma.sync.aligned.m16n8k16.row.col.f32.f16.f16.f32 "
        "{%0,%1,%2,%3},{%4,%5,%6,%7},{%8,%9},{%0,%1,%2,%3};"
        : "+f"(d.x), "+f"(d.y), "+f"(d.z), "+f"(d.w)
        : "r"(a0), "r"(a1), "r"(a2), "r"(a3), "r"(b0), "r"(b1));
}
// fp16-accumulate HMMA: D (2x half2) += A*B
__device__ __forceinline__ void mma16816h(unsigned& d0, unsigned& d1,
                                          unsigned a0, unsigned a1,
                                          unsigned a2, unsigned a3,
                                          unsigned b0, unsigned b1) {
    asm volatile("mma.sync.aligned.m16n8k16.row.col.f16.f16.f16.f16 "
        "{%0,%1},{%2,%3,%4,%5},{%6,%7},{%0,%1};"
        : "+r"(d0), "+r"(d1)
        : "r"(a0), "r"(a1), "r"(a2), "r"(a3), "r"(b0), "r"(b1));
}
__device__ __forceinline__ float ex2(float x) {
    float y; asm("ex2.approx.ftz.f32 %0, %1;" : "=f"(y) : "f"(x)); return y;
}
__device__ __forceinline__ unsigned ex2h2(unsigned x) {
    unsigned y; asm("ex2.approx.f16x2 %0, %1;" : "=r"(y) : "r"(x)); return y;
}
__device__ __forceinline__ unsigned hmax2u(unsigned a, unsigned b) {
    __half2 r = __hmax2(*(__half2*)&a, *(__half2*)&b);
    return *(unsigned*)&r;
}
__device__ __forceinline__ unsigned hsub2u(unsigned a, unsigned b) {
    __half2 r = __hsub2(*(__half2*)&a, *(__half2*)&b);
    return *(unsigned*)&r;
}
__device__ __forceinline__ void cp16(void* dst, const void* src) {
    asm volatile("cp.async.cg.shared.global [%0], [%1], 16;"
                 :: "r"(smaddr(dst)), "l"(src));
}
__device__ __forceinline__ void cp_commit() {
    asm volatile("cp.async.commit_group;");
}
template <int N> __device__ __forceinline__ void cp_wait() {
    asm volatile("cp.async.wait_group %0;" :: "n"(N));
}

// Scratch (device globals; no allocation APIs allowed)
__device__ __half g_xh[BATCH * CCH * NSP];        // group-normed x, half [b][c][n]
__device__ __half g_wq[3 * CCH * CCH];            // w_qkv half [m][k]
__device__ __half g_wo[CCH * CCH];                // w_out half [m][k]
__device__ __half g_q[BATCH * HEADS * NSP * HD];  // [bh][q][d] pre-scaled
__device__ __half g_k[BATCH * HEADS * NSP * HD];  // [bh][k][d]
__device__ __half g_v[BATCH * HEADS * HD * NSP];  // [bh][d][k]
__device__ __half g_o[BATCH * NSP * CCH];         // [b][n][c] attention out

// ---------------------------------------------------------------------------
// Kernel 0: convert weights fp32 -> fp16 (one-shot per launch).
// ---------------------------------------------------------------------------
__global__ void conv_w(const float* __restrict__ wq, const float* __restrict__ wo) {
    int i = blockIdx.x * blockDim.x + threadIdx.x;   // one float4 each
    if (i < 49152) {
        float4 v = ((const float4*)wq)[i];
        __half2* d = (__half2*)&g_wq[i * 4];
        d[0] = __floats2half2_rn(v.x, v.y);
        d[1] = __floats2half2_rn(v.z, v.w);
    } else {
        int j = i - 49152;
        float4 v = ((const float4*)wo)[j];
        __half2* d = (__half2*)&g_wo[j * 4];
        d[0] = __floats2half2_rn(v.x, v.y);
        d[1] = __floats2half2_rn(v.z, v.w);
    }
}

// ---------------------------------------------------------------------------
// Kernel 1: GroupNorm -> half. One block per (b, group).
// ---------------------------------------------------------------------------
__global__ void gn_kernel(const float* __restrict__ x,
                          const float* __restrict__ sc,
                          const float* __restrict__ bi) {
    int bg = blockIdx.x;            // b*8 + g
    int g  = bg & 7;
    const float4* xp = (const float4*)(x + (size_t)bg * 32 * NSP);
    __half2* hp = (__half2*)(g_xh + (size_t)bg * 32 * NSP);

    int t = threadIdx.x;
    float s = 0.f, s2 = 0.f;
    for (int i = t; i < 8192; i += 256) {
        float4 v = xp[i];
        s  += v.x + v.y + v.z + v.w;
        s2 += v.x * v.x + v.y * v.y + v.z * v.z + v.w * v.w;
    }
    __shared__ float r1[256], r2[256];
    r1[t] = s; r2[t] = s2;
    __syncthreads();
    for (int st = 128; st > 0; st >>= 1) {
        if (t < st) { r1[t] += r1[t + st]; r2[t] += r2[t + st]; }
        __syncthreads();
    }
    float mean = r1[0] * (1.f / 32768.f);
    float var  = r2[0] * (1.f / 32768.f) - mean * mean;
    float inv  = rsqrtf(var + 1e-5f);

    for (int i = t; i < 8192; i += 256) {
        int c = g * 32 + (i >> 8);
        float a = inv * sc[c];
        float b = bi[c] - mean * a;
        float4 v = xp[i];
        hp[i * 2]     = __floats2half2_rn(v.x * a + b, v.y * a + b);
        hp[i * 2 + 1] = __floats2half2_rn(v.z * a + b, v.w * a + b);
    }
}

// ---------------------------------------------------------------------------
// Kernel 2/4: fp16 GEMM, cp.async double-buffered. 64m x 64n tile, k-chunk 64.
// MODE 0: qkv.  B = g_xh [k][n] (trans ldsm). Epilogue scatters Q/K/V.
// MODE 1: out.  B = g_o  [n][k] (ldsm).       Epilogue bias + fp32 residual.
// ---------------------------------------------------------------------------
template <int MODE>
__global__ void __launch_bounds__(256)
gemm_h(const __half* __restrict__ A,
       const float* __restrict__ bias,
       const float* __restrict__ resid,
       float* __restrict__ out) {
    __shared__ __half As[2][64][72];
    __shared__ __half Bs[2][64][72];

    int b  = blockIdx.z;
    int m0 = blockIdx.y * 64, n0 = blockIdx.x * 64;
    const __half* Bsrc = (MODE == 0)
        ? g_xh + (size_t)b * CCH * NSP
        : g_o  + (size_t)b * NSP * CCH;

    int tid = threadIdx.x, lane = tid & 31, w = tid >> 5;
    int g = lane >> 2, t = lane & 3;
    int wm = (w & 3) * 16, wn = (w >> 2) * 32;

    int lm  = tid >> 3, lk8 = (tid & 7) * 8;
    int lm2 = lm + 32;

    auto load_tile = [&](int buf, int k0) {
        cp16(&As[buf][lm][lk8],  &A[(size_t)(m0 + lm) * CCH + k0 + lk8]);
        cp16(&As[buf][lm2][lk8], &A[(size_t)(m0 + lm2) * CCH + k0 + lk8]);
        if (MODE == 0) {
            cp16(&Bs[buf][lm][lk8],  &Bsrc[(size_t)(k0 + lm) * NSP + n0 + lk8]);
            cp16(&Bs[buf][lm2][lk8], &Bsrc[(size_t)(k0 + lm2) * NSP + n0 + lk8]);
        } else {
            cp16(&Bs[buf][lm][lk8],  &Bsrc[(size_t)(n0 + lm) * CCH + k0 + lk8]);
            cp16(&Bs[buf][lm2][lk8], &Bsrc[(size_t)(n0 + lm2) * CCH + k0 + lk8]);
        }
    };

    float4 Cf[4] = {{0,0,0,0},{0,0,0,0},{0,0,0,0},{0,0,0,0}};

    load_tile(0, 0);
    cp_commit();

    #pragma unroll
    for (int it = 0; it < 4; it++) {
        int buf = it & 1;
        if (it < 3) { load_tile(buf ^ 1, (it + 1) * 64); cp_commit(); }
        if (it < 3) cp_wait<1>(); else cp_wait<0>();
        __syncthreads();

        unsigned abase = smaddr(&As[buf][wm + (lane & 15)][((lane >> 4) & 1) * 8]);
        unsigned bbase;
        if (MODE == 0)
            bbase = smaddr(&Bs[buf][(lane & 15)][wn + ((lane >> 4) & 1) * 8]);
        else
            bbase = smaddr(&Bs[buf][wn + ((lane >> 4) & 1) * 8 + (lane & 7)]
                                   [((lane >> 3) & 1) * 8]);
        #pragma unroll
        for (int kk = 0; kk < 64; kk += 16) {
            unsigned a0, a1, a2, a3;
            ldsm4(a0, a1, a2, a3, abase + kk * 2);
            #pragma unroll
            for (int p = 0; p < 2; p++) {
                unsigned b0, b1, b2, b3;
                if (MODE == 0)
                    ldsm4t(b0, b1, b2, b3, bbase + kk * 144 + p * 32);
                else
                    ldsm4(b0, b1, b2, b3, bbase + p * 2304 + kk * 2);
                mma16816(Cf[2 * p],     a0, a1, a2, a3, b0, b1);
                mma16816(Cf[2 * p + 1], a0, a1, a2, a3, b2, b3);
            }
        }
        __syncthreads();
    }

    if (MODE == 0) {
        const float qs = 0.17677669529663687f * 1.4426950408889634f;
        int sect = m0 >> 8;                    // 0=Q, 1=K, 2=V
        #pragma unroll
        for (int s = 0; s < 4; s++) {
            int n = n0 + wn + s * 8 + 2 * t;
            #pragma unroll
            for (int rr = 0; rr < 2; rr++) {
                int m = m0 + wm + g + rr * 8;
                float bb = bias[m];
                float v0 = (rr ? Cf[s].z : Cf[s].x) + bb;
                float v1 = (rr ? Cf[s].w : Cf[s].y) + bb;
                int c  = m & 255;
                int bh = b * 8 + (c >> 5);
                int dd = c & 31;
                if (sect == 0) {
                    g_q[((size_t)bh * NSP + n)     * HD + dd] = __float2half_rn(v0 * qs);
                    g_q[((size_t)bh * NSP + n + 1) * HD + dd] = __float2half_rn(v1 * qs);
                } else if (sect == 1) {
                    g_k[((size_t)bh * NSP + n)     * HD + dd] = __float2half_rn(v0);
                    g_k[((size_t)bh * NSP + n + 1) * HD + dd] = __float2half_rn(v1);
                } else {
                    *(__half2*)&g_v[((size_t)bh * HD + dd) * NSP + n] =
                        __floats2half2_rn(v0, v1);
                }
            }
        }
    } else {
        #pragma unroll
        for (int s = 0; s < 4; s++) {
            int n  = n0 + wn + s * 8 + 2 * t;
            int mA = m0 + wm + g, mB = mA + 8;
            float bA = bias[mA], bB = bias[mB];
            size_t iA = ((size_t)b * CCH + mA) * NSP + n;
            size_t iB = ((size_t)b * CCH + mB) * NSP + n;
            float2 rA = *(const float2*)&resid[iA];
            float2 rB = *(const float2*)&resid[iB];
            *(float2*)&out[iA] = make_float2(Cf[s].x + bA + rA.x, Cf[s].y + bA + rA.y);
            *(float2*)&out[iB] = make_float2(Cf[s].z + bB + rB.x, Cf[s].w + bB + rB.y);
        }
    }
}

// ---------------------------------------------------------------------------
// Kernel 3: attention. Block = (b, head, 128-q tile); warp owns 16 q rows.
// fp16-accumulate S (P = ex2.f16x2 output regs, zero conversions), row sums
// via ones-column HMMA, cp.async double-buffered K/V, 1 barrier/iter.
// ---------------------------------------------------------------------------
#define ONES2 0x3C003C00u

__global__ void __launch_bounds__(256, 2) attn_h() {
    __shared__ __half Qs[128][40];      // Q staging
    __shared__ __half Ks[2][128][40];   // [buf][key][d]
    __shared__ __half Vs[2][32][136];   // [buf][d][key]

    int blk = blockIdx.x, qt = blk & 7, bh = blk >> 3;
    const __half* qp = g_q + (size_t)bh * NSP * HD;
    const __half* kp = g_k + (size_t)bh * NSP * HD;
    const __half* vp = g_v + (size_t)bh * HD * NSP;
    int n0 = qt * 128;

    int tid = threadIdx.x, lane = tid & 31, w = tid >> 5;
    int g = lane >> 2, t = lane & 3;

    // load slots for cp.async (2 K chunks + 2 V chunks per thread)
    int krow = tid >> 1, kpart = (tid & 1) * 16;      // 256 thr -> 128 rows x 2
    int vdr  = tid >> 4, vpart = (tid & 15) * 8;

    auto load_kv = [&](int buf, int k0) {
        cp16(&Ks[buf][krow][kpart],      &kp[(size_t)(k0 + krow) * HD + kpart]);
        cp16(&Ks[buf][krow][kpart + 8],  &kp[(size_t)(k0 + krow) * HD + kpart + 8]);
        cp16(&Vs[buf][vdr][vpart],       &vp[(size_t)vdr * NSP + k0 + vpart]);
        cp16(&Vs[buf][vdr + 16][vpart],  &vp[(size_t)(vdr + 16) * NSP + k0 + vpart]);
    };

    // tile 0 in flight while Q stages
    load_kv(0, 0);
    cp_commit();

    #pragma unroll
    for (int r = 0; r < 2; r++) {
        int i = tid + r * 256;
        int row = i >> 2, part = (i & 3) * 8;
        *(float4*)&Qs[row][part] =
            *(const float4*)&qp[(size_t)(n0 + row) * HD + part];
    }
    __syncthreads();
    unsigned qa[8];
    {
        unsigned qaddr = smaddr(&Qs[w * 16 + (lane & 15)][((lane >> 4) & 1) * 8]);
        ldsm4(qa[0], qa[1], qa[2], qa[3], qaddr);        // d 0..15
        ldsm4(qa[4], qa[5], qa[6], qa[7], qaddr + 32);   // d 16..31
    }

    unsigned kaddr0 = smaddr(&Ks[0][((lane >> 4) & 1) * 8 + (lane & 7)]
                                  [((lane >> 3) & 1) * 8]);
    unsigned vaddr0 = smaddr(&Vs[0][((lane >> 4) & 1) * 8 + (lane & 7)]
                                  [((lane >> 3) & 1) * 8]);

    float m0r = -1e30f, m1r = -1e30f;
    float4 Of[5] = {{0,0,0,0},{0,0,0,0},{0,0,0,0},{0,0,0,0},{0,0,0,0}};

    for (int kt = 0; kt < 8; kt++) {
        int buf = kt & 1;
        cp_wait<0>();
        __syncthreads();            // tile kt visible; prev compute done
        if (kt + 1 < 8) { load_kv(buf ^ 1, (kt + 1) * 128); cp_commit(); }

        unsigned kaddr = kaddr0 + buf * 10240;   // 128*40*2
        unsigned vaddr = vaddr0 + buf * 8704;    // 32*136*2

        // ---- S = Q K^T : fp16 accumulate, warp's 16q x 128k ----
        unsigned Sd0[16], Sd1[16];
        #pragma unroll
        for (int s = 0; s < 16; s++) { Sd0[s] = 0u; Sd1[s] = 0u; }
        #pragma unroll
        for (int p = 0; p < 8; p++) {
            unsigned b0, b1, b2, b3;
            ldsm4(b0, b1, b2, b3, kaddr + p * 1280);        // d 0..15
            mma16816h(Sd0[2*p],   Sd1[2*p],   qa[0], qa[1], qa[2], qa[3], b0, b1);
            mma16816h(Sd0[2*p+1], Sd1[2*p+1], qa[0], qa[1], qa[2], qa[3], b2, b3);
            ldsm4(b0, b1, b2, b3, kaddr + p * 1280 + 32);   // d 16..31
            mma16816h(Sd0[2*p],   Sd1[2*p],   qa[4], qa[5], qa[6], qa[7], b0, b1);
            mma16816h(Sd0[2*p+1], Sd1[2*p+1], qa[4], qa[5], qa[6], qa[7], b2, b3);
        }

        // ---- warp-local softmax, fp16 path ----
        unsigned hm0 = Sd0[0], hm1 = Sd1[0];
        #pragma unroll
        for (int s = 1; s < 16; s++) {
            hm0 = hmax2u(hm0, Sd0[s]);
            hm1 = hmax2u(hm1, Sd1[s]);
        }
        __half2 h0 = *(__half2*)&hm0, h1 = *(__half2*)&hm1;
        float mx0 = fmaxf(__low2float(h0), __high2float(h0));
        float mx1 = fmaxf(__low2float(h1), __high2float(h1));
        mx0 = fmaxf(mx0, __shfl_xor_sync(0xffffffffu, mx0, 1));
        mx0 = fmaxf(mx0, __shfl_xor_sync(0xffffffffu, mx0, 2));
        mx1 = fmaxf(mx1, __shfl_xor_sync(0xffffffffu, mx1, 1));
        mx1 = fmaxf(mx1, __shfl_xor_sync(0xffffffffu, mx1, 2));
        float mn0 = fmaxf(m0r, mx0), mn1 = fmaxf(m1r, mx1);
        float c0 = ex2(m0r - mn0), c1 = ex2(m1r - mn1);
        m0r = mn0; m1r = mn1;

        __half2 sub0h = __half2half2(__float2half_rn(mn0));
        __half2 sub1h = __half2half2(__float2half_rn(mn1));
        unsigned su0 = *(unsigned*)&sub0h, su1 = *(unsigned*)&sub1h;
        #pragma unroll
        for (int s = 0; s < 16; s++) {
            Sd0[s] = ex2h2(hsub2u(Sd0[s], su0));   // P row r0, packed half2
            Sd1[s] = ex2h2(hsub2u(Sd1[s], su1));   // P row r1
        }

        // ---- O = O*corr + P V^T (+ ones column -> row sums in Of[4]) ----
        #pragma unroll
        for (int s = 0; s < 5; s++) {
            Of[s].x *= c0; Of[s].y *= c0; Of[s].z *= c1; Of[s].w *= c1;
        }
        #pragma unroll
        for (int kk = 0; kk < 8; kk++) {
            unsigned pa0 = Sd0[2*kk], pa1 = Sd1[2*kk];
            unsigned pa2 = Sd0[2*kk+1], pa3 = Sd1[2*kk+1];
            unsigned b0, b1, b2, b3;
            ldsm4(b0, b1, b2, b3, vaddr + kk * 32);          // d 0..15
            mma16816(Of[0], pa0, pa1, pa2, pa3, b0, b1);
            mma16816(Of[1], pa0, pa1, pa2, pa3, b2, b3);
            ldsm4(b0, b1, b2, b3, vaddr + 4352 + kk * 32);   // d 16..31
            mma16816(Of[2], pa0, pa1, pa2, pa3, b0, b1);
            mma16816(Of[3], pa0, pa1, pa2, pa3, b2, b3);
            mma16816(Of[4], pa0, pa1, pa2, pa3, ONES2, ONES2);  // row sums
        }
    }

    // ---- epilogue: normalize by ones-column sums, store half [b][n][c] ----
    float i0 = 1.f / Of[4].x, i1 = 1.f / Of[4].z;
    int b_ = bh >> 3, h_ = bh & 7;
    int nr0 = n0 + w * 16 + g, nr1 = nr0 + 8;
    #pragma unroll
    for (int s = 0; s < 4; s++) {
        int d = s * 8 + 2 * t;
        size_t iA = ((size_t)b_ * NSP + nr0) * CCH + h_ * 32 + d;
        size_t iB = ((size_t)b_ * NSP + nr1) * CCH + h_ * 32 + d;
        *(__half2*)&g_o[iA] = __floats2half2_rn(Of[s].x * i0, Of[s].y * i0);
        *(__half2*)&g_o[iB] = __floats2half2_rn(Of[s].z * i1, Of[s].w * i1);
    }
}

// ---------------------------------------------------------------------------
extern "C" void kernel_launch(void* const* d_in, const int* in_sizes, int n_in,
                              void* d_out, int out_size) {
    const float* x        = (const float*)d_in[0];
    const float* gn_scale = (const float*)d_in[1];
    const float* gn_bias  = (const float*)d_in[2];
    const float* w_qkv    = (const float*)d_in[3];
    const float* b_qkv    = (const float*)d_in[4];
    const float* w_out    = (const float*)d_in[5];
    const float* b_out    = (const float*)d_in[6];
    float* out = (float*)d_out;

    const __half *pwq, *pwo;
    cudaGetSymbolAddress((void**)&pwq, g_wq);
    cudaGetSymbolAddress((void**)&pwo, g_wo);

    conv_w<<<256, 256>>>(w_qkv, w_out);
    gn_kernel<<<BATCH * 8, 256>>>(x, gn_scale, gn_bias);
    gemm_h<0><<<dim3(16, 12, BATCH), 256>>>(pwq, b_qkv, nullptr, nullptr);
    attn_h<<<BATCH * HEADS * 8, 256>>>();
    gemm_h<1><<<dim3(16, 4, BATCH), 256>>>(pwo, b_out, x, out);
}

// round 8
// speedup vs baseline: 9.0242x; 1.0912x over previous
#include <cuda_runtime.h>
#include <cuda_fp16.h>

// Problem constants: B=8, C=256, H=W=32 -> N=1024, heads=8, hd=32, groups=8.
#define BATCH   8
#define CCH     256
#define NSP     1024
#define HEADS   8
#define HD      32

// ---- mma / ldmatrix / cp.async helpers -------------------------------------
__device__ __forceinline__ unsigned smaddr(const void* p) {
    return (unsigned)__cvta_generic_to_shared(p);
}
__device__ __forceinline__ void ldsm4(unsigned& r0, unsigned& r1,
                                      unsigned& r2, unsigned& r3, unsigned a) {
    asm volatile("ldmatrix.sync.aligned.m8n8.x4.shared.b16 {%0,%1,%2,%3}, [%4];"
                 : "=r"(r0), "=r"(r1), "=r"(r2), "=r"(r3) : "r"(a));
}
__device__ __forceinline__ void ldsm4t(unsigned& r0, unsigned& r1,
                                       unsigned& r2, unsigned& r3, unsigned a) {
    asm volatile("ldmatrix.sync.aligned.m8n8.x4.trans.shared.b16 {%0,%1,%2,%3}, [%4];"
                 : "=r"(r0), "=r"(r1), "=r"(r2), "=r"(r3) : "r"(a));
}
__device__ __forceinline__ void mma16816(float4& d, unsigned a0, unsigned a1,
                                         unsigned a2, unsigned a3,
                                         unsigned b0, unsigned b1) {
    asm volatile("mma.sync.aligned.m16n8k16.row.col.f32.f16.f16.f32 "
        "{%0,%1,%2,%3},{%4,%5,%6,%7},{%8,%9},{%0,%1,%2,%3};"
        : "+f"(d.x), "+f"(d.y), "+f"(d.z), "+f"(d.w)
        : "r"(a0), "r"(a1), "r"(a2), "r"(a3), "r"(b0), "r"(b1));
}
__device__ __forceinline__ void mma16816h(unsigned& d0, unsigned& d1,
                                          unsigned a0, unsigned a1,
                                          unsigned a2, unsigned a3,
                                          unsigned b0, unsigned b1) {
    asm volatile("mma.sync.aligned.m16n8k16.row.col.f16.f16.f16.f16 "
        "{%0,%1},{%2,%3,%4,%5},{%6,%7},{%0,%1};"
        : "+r"(d0), "+r"(d1)
        : "r"(a0), "r"(a1), "r"(a2), "r"(a3), "r"(b0), "r"(b1));
}
__device__ __forceinline__ float ex2(float x) {
    float y; asm("ex2.approx.ftz.f32 %0, %1;" : "=f"(y) : "f"(x)); return y;
}
__device__ __forceinline__ unsigned ex2h2(unsigned x) {
    unsigned y; asm("ex2.approx.f16x2 %0, %1;" : "=r"(y) : "r"(x)); return y;
}
__device__ __forceinline__ unsigned hmax2u(unsigned a, unsigned b) {
    __half2 r = __hmax2(*(__half2*)&a, *(__half2*)&b);
    return *(unsigned*)&r;
}
__device__ __forceinline__ unsigned hsub2u(unsigned a, unsigned b) {
    __half2 r = __hsub2(*(__half2*)&a, *(__half2*)&b);
    return *(unsigned*)&r;
}
__device__ __forceinline__ void cp16(void* dst, const void* src) {
    asm volatile("cp.async.cg.shared.global [%0], [%1], 16;"
                 :: "r"(smaddr(dst)), "l"(src));
}
__device__ __forceinline__ void cp_commit() {
    asm volatile("cp.async.commit_group;");
}
template <int N> __device__ __forceinline__ void cp_wait() {
    asm volatile("cp.async.wait_group %0;" :: "n"(N));
}

// Scratch (device globals; no allocation APIs allowed)
__device__ __half g_xh[BATCH * CCH * NSP];        // group-normed x, half [b][c][n]
__device__ __half g_wq[3 * CCH * CCH];            // w_qkv half [m][k]
__device__ __half g_wo[CCH * CCH];                // w_out half [m][k]
__device__ __half g_q[BATCH * HEADS * NSP * HD];  // [bh][q][d] pre-scaled
__device__ __half g_k[BATCH * HEADS * NSP * HD];  // [bh][k][d]
__device__ __half g_v[BATCH * HEADS * HD * NSP];  // [bh][d][k]
__device__ __half g_o[BATCH * NSP * CCH];         // [b][n][c] attention out

// ---------------------------------------------------------------------------
// Kernel 1: fused (a) GroupNorm -> half  (blocks 0..63)
//           (b) weight convert fp32->fp16 (blocks 64..319)
// ---------------------------------------------------------------------------
__global__ void prep_kernel(const float* __restrict__ x,
                            const float* __restrict__ sc,
                            const float* __restrict__ bi,
                            const float* __restrict__ wq,
                            const float* __restrict__ wo) {
    if (blockIdx.x >= 64) {
        int i = (blockIdx.x - 64) * 256 + threadIdx.x;   // one float4 each
        if (i < 49152) {
            float4 v = ((const float4*)wq)[i];
            __half2* d = (__half2*)&g_wq[i * 4];
            d[0] = __floats2half2_rn(v.x, v.y);
            d[1] = __floats2half2_rn(v.z, v.w);
        } else {
            int j = i - 49152;
            float4 v = ((const float4*)wo)[j];
            __half2* d = (__half2*)&g_wo[j * 4];
            d[0] = __floats2half2_rn(v.x, v.y);
            d[1] = __floats2half2_rn(v.z, v.w);
        }
        return;
    }
    int bg = blockIdx.x;            // b*8 + g
    int g  = bg & 7;
    const float4* xp = (const float4*)(x + (size_t)bg * 32 * NSP);
    __half2* hp = (__half2*)(g_xh + (size_t)bg * 32 * NSP);

    int t = threadIdx.x;
    float s = 0.f, s2 = 0.f;
    for (int i = t; i < 8192; i += 256) {
        float4 v = xp[i];
        s  += v.x + v.y + v.z + v.w;
        s2 += v.x * v.x + v.y * v.y + v.z * v.z + v.w * v.w;
    }
    __shared__ float r1[256], r2[256];
    r1[t] = s; r2[t] = s2;
    __syncthreads();
    for (int st = 128; st > 0; st >>= 1) {
        if (t < st) { r1[t] += r1[t + st]; r2[t] += r2[t + st]; }
        __syncthreads();
    }
    float mean = r1[0] * (1.f / 32768.f);
    float var  = r2[0] * (1.f / 32768.f) - mean * mean;
    float inv  = rsqrtf(var + 1e-5f);

    for (int i = t; i < 8192; i += 256) {
        int c = g * 32 + (i >> 8);
        float a = inv * sc[c];
        float b = bi[c] - mean * a;
        float4 v = xp[i];
        hp[i * 2]     = __floats2half2_rn(v.x * a + b, v.y * a + b);
        hp[i * 2 + 1] = __floats2half2_rn(v.z * a + b, v.w * a + b);
    }
}

// ---------------------------------------------------------------------------
// Kernel 2/4: fp16 GEMM, cp.async double-buffered. 64m x 64n tile, k-chunk 64.
// MODE 0: qkv.  B = g_xh [k][n] (trans ldsm). Epilogue scatters Q/K/V.
// MODE 1: out.  B = g_o  [n][k] (ldsm).       Epilogue bias + fp32 residual.
// ---------------------------------------------------------------------------
template <int MODE>
__global__ void __launch_bounds__(256)
gemm_h(const __half* __restrict__ A,
       const float* __restrict__ bias,
       const float* __restrict__ resid,
       float* __restrict__ out) {
    __shared__ __half As[2][64][72];
    __shared__ __half Bs[2][64][72];

    int b  = blockIdx.z;
    int m0 = blockIdx.y * 64, n0 = blockIdx.x * 64;
    const __half* Bsrc = (MODE == 0)
        ? g_xh + (size_t)b * CCH * NSP
        : g_o  + (size_t)b * NSP * CCH;

    int tid = threadIdx.x, lane = tid & 31, w = tid >> 5;
    int g = lane >> 2, t = lane & 3;
    int wm = (w & 3) * 16, wn = (w >> 2) * 32;

    int lm  = tid >> 3, lk8 = (tid & 7) * 8;
    int lm2 = lm + 32;

    auto load_tile = [&](int buf, int k0) {
        cp16(&As[buf][lm][lk8],  &A[(size_t)(m0 + lm) * CCH + k0 + lk8]);
        cp16(&As[buf][lm2][lk8], &A[(size_t)(m0 + lm2) * CCH + k0 + lk8]);
        if (MODE == 0) {
            cp16(&Bs[buf][lm][lk8],  &Bsrc[(size_t)(k0 + lm) * NSP + n0 + lk8]);
            cp16(&Bs[buf][lm2][lk8], &Bsrc[(size_t)(k0 + lm2) * NSP + n0 + lk8]);
        } else {
            cp16(&Bs[buf][lm][lk8],  &Bsrc[(size_t)(n0 + lm) * CCH + k0 + lk8]);
            cp16(&Bs[buf][lm2][lk8], &Bsrc[(size_t)(n0 + lm2) * CCH + k0 + lk8]);
        }
    };

    float4 Cf[4] = {{0,0,0,0},{0,0,0,0},{0,0,0,0},{0,0,0,0}};

    load_tile(0, 0);
    cp_commit();

    #pragma unroll
    for (int it = 0; it < 4; it++) {
        int buf = it & 1;
        if (it < 3) { load_tile(buf ^ 1, (it + 1) * 64); cp_commit(); }
        if (it < 3) cp_wait<1>(); else cp_wait<0>();
        __syncthreads();

        unsigned abase = smaddr(&As[buf][wm + (lane & 15)][((lane >> 4) & 1) * 8]);
        unsigned bbase;
        if (MODE == 0)
            bbase = smaddr(&Bs[buf][(lane & 15)][wn + ((lane >> 4) & 1) * 8]);
        else
            bbase = smaddr(&Bs[buf][wn + ((lane >> 4) & 1) * 8 + (lane & 7)]
                                   [((lane >> 3) & 1) * 8]);
        #pragma unroll
        for (int kk = 0; kk < 64; kk += 16) {
            unsigned a0, a1, a2, a3;
            ldsm4(a0, a1, a2, a3, abase + kk * 2);
            #pragma unroll
            for (int p = 0; p < 2; p++) {
                unsigned b0, b1, b2, b3;
                if (MODE == 0)
                    ldsm4t(b0, b1, b2, b3, bbase + kk * 144 + p * 32);
                else
                    ldsm4(b0, b1, b2, b3, bbase + p * 2304 + kk * 2);
                mma16816(Cf[2 * p],     a0, a1, a2, a3, b0, b1);
                mma16816(Cf[2 * p + 1], a0, a1, a2, a3, b2, b3);
            }
        }
        __syncthreads();
    }

    if (MODE == 0) {
        const float qs = 0.17677669529663687f * 1.4426950408889634f;
        int sect = m0 >> 8;                    // 0=Q, 1=K, 2=V
        #pragma unroll
        for (int s = 0; s < 4; s++) {
            int n = n0 + wn + s * 8 + 2 * t;
            #pragma unroll
            for (int rr = 0; rr < 2; rr++) {
                int m = m0 + wm + g + rr * 8;
                float bb = bias[m];
                float v0 = (rr ? Cf[s].z : Cf[s].x) + bb;
                float v1 = (rr ? Cf[s].w : Cf[s].y) + bb;
                int c  = m & 255;
                int bh = b * 8 + (c >> 5);
                int dd = c & 31;
                if (sect == 0) {
                    g_q[((size_t)bh * NSP + n)     * HD + dd] = __float2half_rn(v0 * qs);
                    g_q[((size_t)bh * NSP + n + 1) * HD + dd] = __float2half_rn(v1 * qs);
                } else if (sect == 1) {
                    g_k[((size_t)bh * NSP + n)     * HD + dd] = __float2half_rn(v0);
                    g_k[((size_t)bh * NSP + n + 1) * HD + dd] = __float2half_rn(v1);
                } else {
                    *(__half2*)&g_v[((size_t)bh * HD + dd) * NSP + n] =
                        __floats2half2_rn(v0, v1);
                }
            }
        }
    } else {
        #pragma unroll
        for (int s = 0; s < 4; s++) {
            int n  = n0 + wn + s * 8 + 2 * t;
            int mA = m0 + wm + g, mB = mA + 8;
            float bA = bias[mA], bB = bias[mB];
            size_t iA = ((size_t)b * CCH + mA) * NSP + n;
            size_t iB = ((size_t)b * CCH + mB) * NSP + n;
            float2 rA = *(const float2*)&resid[iA];
            float2 rB = *(const float2*)&resid[iB];
            *(float2*)&out[iA] = make_float2(Cf[s].x + bA + rA.x, Cf[s].y + bA + rA.y);
            *(float2*)&out[iB] = make_float2(Cf[s].z + bB + rB.x, Cf[s].w + bB + rB.y);
        }
    }
}

// ---------------------------------------------------------------------------
// Kernel 3: attention. Block = (b, head, 128-q tile); warp owns 16 q rows.
// KT=64 (16 iterations) to cut registers/smem for 3 CTAs/SM occupancy.
// fp16-acc S, ex2.f16x2 softmax, ones-column row sums, cp.async dbuf K/V.
// ---------------------------------------------------------------------------
#define ONES2 0x3C003C00u

__global__ void __launch_bounds__(256, 3) attn_h() {
    __shared__ __half Qs[128][40];     // Q staging (10240 B)
    __shared__ __half Ks[2][64][40];   // [buf][key][d]  (2x 5120 B)
    __shared__ __half Vs[2][32][72];   // [buf][d][key]  (2x 4608 B)

    int blk = blockIdx.x, qt = blk & 7, bh = blk >> 3;
    const __half* qp = g_q + (size_t)bh * NSP * HD;
    const __half* kp = g_k + (size_t)bh * NSP * HD;
    const __half* vp = g_v + (size_t)bh * HD * NSP;
    int n0 = qt * 128;

    int tid = threadIdx.x, lane = tid & 31, w = tid >> 5;
    int g = lane >> 2, t = lane & 3;

    // cp.async slots: K tile 64x32 halves = 256 16B-chunks; V tile 32x64 = 256.
    int kr = tid >> 2, kc = (tid & 3) * 8;     // K: row 0..63, col 0/8/16/24
    int vr = tid >> 3, vc = (tid & 7) * 8;     // V: row 0..31, col 0..56

    auto load_kv = [&](int buf, int k0) {
        cp16(&Ks[buf][kr][kc], &kp[(size_t)(k0 + kr) * HD + kc]);
        cp16(&Vs[buf][vr][vc], &vp[(size_t)vr * NSP + k0 + vc]);
    };

    load_kv(0, 0);
    cp_commit();

    #pragma unroll
    for (int r = 0; r < 2; r++) {
        int i = tid + r * 256;
        int row = i >> 2, part = (i & 3) * 8;
        *(float4*)&Qs[row][part] =
            *(const float4*)&qp[(size_t)(n0 + row) * HD + part];
    }
    __syncthreads();
    unsigned qa[8];
    {
        unsigned qaddr = smaddr(&Qs[w * 16 + (lane & 15)][((lane >> 4) & 1) * 8]);
        ldsm4(qa[0], qa[1], qa[2], qa[3], qaddr);        // d 0..15
        ldsm4(qa[4], qa[5], qa[6], qa[7], qaddr + 32);   // d 16..31
    }

    unsigned kaddr0 = smaddr(&Ks[0][((lane >> 4) & 1) * 8 + (lane & 7)]
                                  [((lane >> 3) & 1) * 8]);
    unsigned vaddr0 = smaddr(&Vs[0][((lane >> 4) & 1) * 8 + (lane & 7)]
                                  [((lane >> 3) & 1) * 8]);

    float m0r = -1e30f, m1r = -1e30f;
    float4 Of[5] = {{0,0,0,0},{0,0,0,0},{0,0,0,0},{0,0,0,0},{0,0,0,0}};

    for (int kt = 0; kt < 16; kt++) {
        int buf = kt & 1;
        cp_wait<0>();
        __syncthreads();            // tile kt visible; prev compute done
        if (kt + 1 < 16) { load_kv(buf ^ 1, (kt + 1) * 64); cp_commit(); }

        unsigned kaddr = kaddr0 + buf * 5120;   // 64*40*2
        unsigned vaddr = vaddr0 + buf * 4608;   // 32*72*2

        // ---- S = Q K^T : fp16 accumulate, warp's 16q x 64k ----
        unsigned Sd0[8], Sd1[8];
        #pragma unroll
        for (int s = 0; s < 8; s++) { Sd0[s] = 0u; Sd1[s] = 0u; }
        #pragma unroll
        for (int p = 0; p < 4; p++) {            // 16 keys per p
            unsigned b0, b1, b2, b3;
            ldsm4(b0, b1, b2, b3, kaddr + p * 1280);        // d 0..15
            mma16816h(Sd0[2*p],   Sd1[2*p],   qa[0], qa[1], qa[2], qa[3], b0, b1);
            mma16816h(Sd0[2*p+1], Sd1[2*p+1], qa[0], qa[1], qa[2], qa[3], b2, b3);
            ldsm4(b0, b1, b2, b3, kaddr + p * 1280 + 32);   // d 16..31
            mma16816h(Sd0[2*p],   Sd1[2*p],   qa[4], qa[5], qa[6], qa[7], b0, b1);
            mma16816h(Sd0[2*p+1], Sd1[2*p+1], qa[4], qa[5], qa[6], qa[7], b2, b3);
        }

        // ---- warp-local softmax, fp16 path ----
        unsigned hm0 = Sd0[0], hm1 = Sd1[0];
        #pragma unroll
        for (int s = 1; s < 8; s++) {
            hm0 = hmax2u(hm0, Sd0[s]);
            hm1 = hmax2u(hm1, Sd1[s]);
        }
        __half2 h0 = *(__half2*)&hm0, h1 = *(__half2*)&hm1;
        float mx0 = fmaxf(__low2float(h0), __high2float(h0));
        float mx1 = fmaxf(__low2float(h1), __high2float(h1));
        mx0 = fmaxf(mx0, __shfl_xor_sync(0xffffffffu, mx0, 1));
        mx0 = fmaxf(mx0, __shfl_xor_sync(0xffffffffu, mx0, 2));
        mx1 = fmaxf(mx1, __shfl_xor_sync(0xffffffffu, mx1, 1));
        mx1 = fmaxf(mx1, __shfl_xor_sync(0xffffffffu, mx1, 2));
        float mn0 = fmaxf(m0r, mx0), mn1 = fmaxf(m1r, mx1);
        float c0 = ex2(m0r - mn0), c1 = ex2(m1r - mn1);
        m0r = mn0; m1r = mn1;

        __half2 sub0h = __half2half2(__float2half_rn(mn0));
        __half2 sub1h = __half2half2(__float2half_rn(mn1));
        unsigned su0 = *(unsigned*)&sub0h, su1 = *(unsigned*)&sub1h;
        #pragma unroll
        for (int s = 0; s < 8; s++) {
            Sd0[s] = ex2h2(hsub2u(Sd0[s], su0));   // P row r0
            Sd1[s] = ex2h2(hsub2u(Sd1[s], su1));   // P row r1
        }

        // ---- O = O*corr + P V^T (+ ones column -> row sums in Of[4]) ----
        #pragma unroll
        for (int s = 0; s < 5; s++) {
            Of[s].x *= c0; Of[s].y *= c0; Of[s].z *= c1; Of[s].w *= c1;
        }
        #pragma unroll
        for (int kk = 0; kk < 4; kk++) {           // 16 keys per kk
            unsigned pa0 = Sd0[2*kk], pa1 = Sd1[2*kk];
            unsigned pa2 = Sd0[2*kk+1], pa3 = Sd1[2*kk+1];
            unsigned b0, b1, b2, b3;
            ldsm4(b0, b1, b2, b3, vaddr + kk * 32);          // d 0..15
            mma16816(Of[0], pa0, pa1, pa2, pa3, b0, b1);
            mma16816(Of[1], pa0, pa1, pa2, pa3, b2, b3);
            ldsm4(b0, b1, b2, b3, vaddr + 2304 + kk * 32);   // d 16..31
            mma16816(Of[2], pa0, pa1, pa2, pa3, b0, b1);
            mma16816(Of[3], pa0, pa1, pa2, pa3, b2, b3);
            mma16816(Of[4], pa0, pa1, pa2, pa3, ONES2, ONES2);  // row sums
        }
    }

    // ---- epilogue: normalize by ones-column sums, store half [b][n][c] ----
    float i0 = 1.f / Of[4].x, i1 = 1.f / Of[4].z;
    int b_ = bh >> 3, h_ = bh & 7;
    int nr0 = n0 + w * 16 + g, nr1 = nr0 + 8;
    #pragma unroll
    for (int s = 0; s < 4; s++) {
        int d = s * 8 + 2 * t;
        size_t iA = ((size_t)b_ * NSP + nr0) * CCH + h_ * 32 + d;
        size_t iB = ((size_t)b_ * NSP + nr1) * CCH + h_ * 32 + d;
        *(__half2*)&g_o[iA] = __floats2half2_rn(Of[s].x * i0, Of[s].y * i0);
        *(__half2*)&g_o[iB] = __floats2half2_rn(Of[s].z * i1, Of[s].w * i1);
    }
}

// ---------------------------------------------------------------------------
extern "C" void kernel_launch(void* const* d_in, const int* in_sizes, int n_in,
                              void* d_out, int out_size) {
    const float* x        = (const float*)d_in[0];
    const float* gn_scale = (const float*)d_in[1];
    const float* gn_bias  = (const float*)d_in[2];
    const float* w_qkv    = (const float*)d_in[3];
    const float* b_qkv    = (const float*)d_in[4];
    const float* w_out    = (const float*)d_in[5];
    const float* b_out    = (const float*)d_in[6];
    float* out = (float*)d_out;

    const __half *pwq, *pwo;
    cudaGetSymbolAddress((void**)&pwq, g_wq);
    cudaGetSymbolAddress((void**)&pwo, g_wo);

    // 1. GroupNorm -> half + weight conversion (fused launch)
    prep_kernel<<<320, 256>>>(x, gn_scale, gn_bias, w_qkv, w_out);
    // 2. QKV projection -> half Q/K/V in attention layouts
    gemm_h<0><<<dim3(16, 12, BATCH), 256>>>(pwq, b_qkv, nullptr, nullptr);
    // 3. Attention -> half [b][n][c]
    attn_h<<<BATCH * HEADS * 8, 256>>>();
    // 4. Output projection + bias + fp32 residual
    gemm_h<1><<<dim3(16, 4, BATCH), 256>>>(pwo, b_out, x, out);
}